// round 1
// baseline (speedup 1.0000x reference)
#include <cuda_runtime.h>
#include <cstdint>

#define NBATCH 8
#define LPIX 4096

// ---------------- scratch (static device globals; no allocation) ----------------
__device__ float g_y0[(size_t)NBATCH * 512 * LPIX];     // cv1 output (b,512,4096)
__device__ float g_t0[(size_t)NBATCH * 256 * LPIX];
__device__ float g_b1[(size_t)NBATCH * 256 * LPIX];
__device__ float g_t1[(size_t)NBATCH * 256 * LPIX];
__device__ float g_b2[(size_t)NBATCH * 256 * LPIX];
__device__ float g_value[(size_t)NBATCH * LPIX * 256]; // (b,l,d)
__device__ float g_off[(size_t)NBATCH * LPIX * 64];    // (b,l,64)
__device__ float g_awl[(size_t)NBATCH * LPIX * 32];    // (b,l,32) raw logits
__device__ float g_samp[(size_t)NBATCH * LPIX * 256];  // (b,l,d)
__device__ float g_attn[(size_t)NBATCH * 256 * LPIX];  // (b,d,l)  (pre-transposed for cv2)

__device__ __forceinline__ float silu_f(float v) { return v / (1.f + __expf(-v)); }

// 64x64x16 tile inner product: 2x LDS.128 + 16 FFMA per k
__device__ __forceinline__ void tile_mma(const float (*As)[64], const float (*Bs)[64],
                                         float acc[4][4], int tx, int ty) {
#pragma unroll
    for (int kk = 0; kk < 16; kk++) {
        float4 a4 = *(const float4*)&As[kk][ty << 2];
        float4 b4 = *(const float4*)&Bs[kk][tx << 2];
        acc[0][0] += a4.x * b4.x; acc[0][1] += a4.x * b4.y; acc[0][2] += a4.x * b4.z; acc[0][3] += a4.x * b4.w;
        acc[1][0] += a4.y * b4.x; acc[1][1] += a4.y * b4.y; acc[1][2] += a4.y * b4.z; acc[1][3] += a4.y * b4.w;
        acc[2][0] += a4.z * b4.x; acc[2][1] += a4.z * b4.y; acc[2][2] += a4.z * b4.z; acc[2][3] += a4.z * b4.w;
        acc[3][0] += a4.w * b4.x; acc[3][1] += a4.w * b4.y; acc[3][2] += a4.w * b4.z; acc[3][3] += a4.w * b4.w;
    }
}

#define ACC_INIT()                     \
    float acc[4][4];                   \
    _Pragma("unroll") for (int _i = 0; _i < 4; _i++) \
    _Pragma("unroll") for (int _j = 0; _j < 4; _j++) acc[_i][_j] = 0.f;

// ---------------- cv1: 1x1 conv 512->512 + silu -> g_y0 ----------------
__global__ void k_cv1(const float* __restrict__ x, const float* __restrict__ w) {
    __shared__ float As[16][64];
    __shared__ float Bs[16][64];
    ACC_INIT();
    const int tid = threadIdx.x;
    const int tx = tid & 15, ty = tid >> 4;
    const int b = blockIdx.z;
    const int n0 = blockIdx.x << 6, m0 = blockIdx.y << 6;
    const float* xb = x + (size_t)b * 512 * LPIX;
    const int alm = tid >> 2, alk = (tid & 3) << 2;
    const int blk = tid >> 4, bln = (tid & 15) << 2;

    for (int k0 = 0; k0 < 512; k0 += 16) {
        float4 av = *(const float4*)&w[(size_t)(m0 + alm) * 512 + k0 + alk];
        As[alk + 0][alm] = av.x; As[alk + 1][alm] = av.y;
        As[alk + 2][alm] = av.z; As[alk + 3][alm] = av.w;
        *(float4*)&Bs[blk][bln] = *(const float4*)&xb[(size_t)(k0 + blk) * LPIX + n0 + bln];
        __syncthreads();
        tile_mma(As, Bs, acc, tx, ty);
        __syncthreads();
    }
    float* ob = g_y0 + (size_t)b * 512 * LPIX;
#pragma unroll
    for (int i = 0; i < 4; i++) {
        float4 o;
        o.x = silu_f(acc[i][0]); o.y = silu_f(acc[i][1]);
        o.z = silu_f(acc[i][2]); o.w = silu_f(acc[i][3]);
        *(float4*)&ob[(size_t)(m0 + (ty << 2) + i) * LPIX + n0 + (tx << 2)] = o;
    }
}

// ---------------- 3x3 conv 256->256 + silu (implicit GEMM, K=2304) ----------------
__global__ void k_conv3(int which, const float* __restrict__ w) {
    const float* in; float* out; size_t bstride;
    if (which == 0)      { in = g_y0 + (size_t)256 * LPIX; out = g_t0; bstride = (size_t)512 * LPIX; }
    else if (which == 1) { in = g_t0; out = g_b1; bstride = (size_t)256 * LPIX; }
    else if (which == 2) { in = g_b1; out = g_t1; bstride = (size_t)256 * LPIX; }
    else                 { in = g_t1; out = g_b2; bstride = (size_t)256 * LPIX; }

    __shared__ float As[16][64];
    __shared__ float Bs[16][64];
    ACC_INIT();
    const int tid = threadIdx.x;
    const int tx = tid & 15, ty = tid >> 4;
    const int b = blockIdx.z;
    const int n0 = blockIdx.x << 6, m0 = blockIdx.y << 6;
    const float* ib = in + (size_t)b * bstride;
    const int alm = tid >> 2, alk = (tid & 3) << 2;
    const int blk = tid >> 4, bln = (tid & 15) << 2;

    for (int k0 = 0; k0 < 2304; k0 += 16) {
        float4 av = *(const float4*)&w[(size_t)(m0 + alm) * 2304 + k0 + alk];
        As[alk + 0][alm] = av.x; As[alk + 1][alm] = av.y;
        As[alk + 2][alm] = av.z; As[alk + 3][alm] = av.w;

        int k = k0 + blk;
        int ic = k / 9;
        int j = k - ic * 9;
        int jd3 = j / 3;
        int ky = jd3 - 1;
        int kx = j - jd3 * 3 - 1;
        const float* ip = ib + (size_t)ic * LPIX;
        float4 bv;
#pragma unroll
        for (int e = 0; e < 4; e++) {
            int pn = n0 + bln + e;
            int sy = (pn >> 6) + ky;
            int sx = (pn & 63) + kx;
            float t = 0.f;
            if ((unsigned)sy < 64u && (unsigned)sx < 64u) t = __ldg(&ip[(sy << 6) + sx]);
            (&bv.x)[e] = t;
        }
        *(float4*)&Bs[blk][bln] = bv;
        __syncthreads();
        tile_mma(As, Bs, acc, tx, ty);
        __syncthreads();
    }
    float* ob = out + (size_t)b * 256 * LPIX;
#pragma unroll
    for (int i = 0; i < 4; i++) {
        float4 o;
        o.x = silu_f(acc[i][0]); o.y = silu_f(acc[i][1]);
        o.z = silu_f(acc[i][2]); o.w = silu_f(acc[i][3]);
        *(float4*)&ob[(size_t)(m0 + (ty << 2) + i) * LPIX + n0 + (tx << 2)] = o;
    }
}

// ---------------- q projections: out[(b*L+l)*N + n] = sum_c b2[b][c][l] * w[c][n] + bias ----------------
__global__ void k_proj(int which, const float* __restrict__ w, const float* __restrict__ bias) {
    int N; float* out;
    if (which == 0)      { N = 256; out = g_value; }
    else if (which == 1) { N = 64;  out = g_off; }
    else                 { N = 32;  out = g_awl; }

    __shared__ float As[16][64];   // [k(c)][m(l)]
    __shared__ float Bs[16][64];
    ACC_INIT();
    const int tid = threadIdx.x;
    const int tx = tid & 15, ty = tid >> 4;
    const int b = blockIdx.z;
    const int n0 = blockIdx.x << 6, m0 = blockIdx.y << 6;
    const float* sb = g_b2 + (size_t)b * 256 * LPIX;
    const int lk = tid >> 4, lm = (tid & 15) << 2;

    for (int k0 = 0; k0 < 256; k0 += 16) {
        *(float4*)&As[lk][lm] = *(const float4*)&sb[(size_t)(k0 + lk) * LPIX + m0 + lm];
#pragma unroll
        for (int e = 0; e < 4; e++) {
            int n = n0 + lm + e;
            Bs[lk][lm + e] = (n < N) ? w[(size_t)(k0 + lk) * N + n] : 0.f;
        }
        __syncthreads();
        tile_mma(As, Bs, acc, tx, ty);
        __syncthreads();
    }
    float* ob = out + (size_t)b * LPIX * N;
#pragma unroll
    for (int i = 0; i < 4; i++) {
        int m = m0 + (ty << 2) + i;
#pragma unroll
        for (int j2 = 0; j2 < 4; j2++) {
            int n = n0 + (tx << 2) + j2;
            if (n < N) ob[(size_t)m * N + n] = acc[i][j2] + bias[n];
        }
    }
}

// ---------------- deformable sampling + softmax over 4 points ----------------
__global__ void k_sample(const float* __restrict__ bbox) {
    int g = blockIdx.x * blockDim.x + threadIdx.x;
    if (g >= NBATCH * LPIX * 64) return;   // 8*4096*8heads*8quads
    int d4 = g & 7;
    int h  = (g >> 3) & 7;
    int l  = (g >> 6) & 4095;
    int b  = g >> 18;
    size_t bl = (size_t)b * LPIX + l;
    float bx = bbox[bl * 2 + 0];
    float by = bbox[bl * 2 + 1];
    const float* op = g_off + bl * 64 + h * 8;
    const float* ap = g_awl + bl * 32 + h * 4;

    float l0 = ap[0], l1 = ap[1], l2 = ap[2], l3 = ap[3];
    float mx = fmaxf(fmaxf(l0, l1), fmaxf(l2, l3));
    float e0 = __expf(l0 - mx), e1 = __expf(l1 - mx), e2 = __expf(l2 - mx), e3 = __expf(l3 - mx);
    float inv = 1.f / (e0 + e1 + e2 + e3);
    float wp[4] = {e0 * inv, e1 * inv, e2 * inv, e3 * inv};

    const float* vb = g_value + ((size_t)b * LPIX) * 256 + h * 32 + (d4 << 2);
    float4 acc = make_float4(0.f, 0.f, 0.f, 0.f);
#pragma unroll
    for (int p = 0; p < 4; p++) {
        // match reference rounding: loc = bbox + off/64; g = loc*64 - 0.5
        float lx = bx + op[p * 2 + 0] * 0.015625f;
        float ly = by + op[p * 2 + 1] * 0.015625f;
        float gx = lx * 64.f - 0.5f;
        float gy = ly * 64.f - 0.5f;
        float fx = floorf(gx), fy = floorf(gy);
        float wx1 = gx - fx, wy1 = gy - fy;
        float wx0 = 1.f - wx1, wy0 = 1.f - wy1;
        int ix = (int)fx, iy = (int)fy;
        float awp = wp[p];
#pragma unroll
        for (int c2 = 0; c2 < 4; c2++) {
            int cx = ix + (c2 & 1);
            int cy = iy + (c2 >> 1);
            if ((unsigned)cx < 64u && (unsigned)cy < 64u) {
                float wgt = awp * ((c2 & 1) ? wx1 : wx0) * ((c2 >> 1) ? wy1 : wy0);
                float4 v = *(const float4*)&vb[(size_t)((cy << 6) + cx) * 256];
                acc.x += wgt * v.x; acc.y += wgt * v.y;
                acc.z += wgt * v.z; acc.w += wgt * v.w;
            }
        }
    }
    *(float4*)&g_samp[bl * 256 + h * 32 + (d4 << 2)] = acc;
}

// ---------------- out projection, stored transposed: g_attn[(b*256+d)*L + l] ----------------
__global__ void k_outproj(const float* __restrict__ w, const float* __restrict__ bias) {
    __shared__ float As[16][64];
    __shared__ float Bs[16][64];
    ACC_INIT();
    const int tid = threadIdx.x;
    const int tx = tid & 15, ty = tid >> 4;
    const int b = blockIdx.z;
    const int n0 = blockIdx.x << 6, m0 = blockIdx.y << 6;   // m = l, n = d
    const float* sb = g_samp + (size_t)b * LPIX * 256;
    const int alm = tid >> 2, alk = (tid & 3) << 2;
    const int blk = tid >> 4, bln = (tid & 15) << 2;

    for (int k0 = 0; k0 < 256; k0 += 16) {
        float4 av = *(const float4*)&sb[(size_t)(m0 + alm) * 256 + k0 + alk];
        As[alk + 0][alm] = av.x; As[alk + 1][alm] = av.y;
        As[alk + 2][alm] = av.z; As[alk + 3][alm] = av.w;
        *(float4*)&Bs[blk][bln] = *(const float4*)&w[(size_t)(k0 + blk) * 256 + n0 + bln];
        __syncthreads();
        tile_mma(As, Bs, acc, tx, ty);
        __syncthreads();
    }
#pragma unroll
    for (int j2 = 0; j2 < 4; j2++) {
        int n = n0 + (tx << 2) + j2;
        float bi = bias[n];
#pragma unroll
        for (int i = 0; i < 4; i++) {
            int m = m0 + (ty << 2) + i;
            g_attn[((size_t)b * 256 + n) * LPIX + m] = acc[i][j2] + bi;
        }
    }
}

// ---------------- cv2: 1x1 conv over concat(1280) -> 512 + silu -> d_out ----------------
__global__ void k_cv2(const float* __restrict__ w, float* __restrict__ out) {
    __shared__ float As[16][64];
    __shared__ float Bs[16][64];
    ACC_INIT();
    const int tid = threadIdx.x;
    const int tx = tid & 15, ty = tid >> 4;
    const int b = blockIdx.z;
    const int n0 = blockIdx.x << 6, m0 = blockIdx.y << 6;
    const int alm = tid >> 2, alk = (tid & 3) << 2;
    const int blk = tid >> 4, bln = (tid & 15) << 2;

    for (int k0 = 0; k0 < 1280; k0 += 16) {
        float4 av = *(const float4*)&w[(size_t)(m0 + alm) * 1280 + k0 + alk];
        As[alk + 0][alm] = av.x; As[alk + 1][alm] = av.y;
        As[alk + 2][alm] = av.z; As[alk + 3][alm] = av.w;

        int c = k0 + blk;
        const float* src;
        if (c < 512)       src = g_y0   + ((size_t)b * 512 + c)          * LPIX;
        else if (c < 768)  src = g_b1   + ((size_t)b * 256 + (c - 512))  * LPIX;
        else if (c < 1024) src = g_b2   + ((size_t)b * 256 + (c - 768))  * LPIX;
        else               src = g_attn + ((size_t)b * 256 + (c - 1024)) * LPIX;
        *(float4*)&Bs[blk][bln] = *(const float4*)&src[n0 + bln];
        __syncthreads();
        tile_mma(As, Bs, acc, tx, ty);
        __syncthreads();
    }
    float* ob = out + (size_t)b * 512 * LPIX;
#pragma unroll
    for (int i = 0; i < 4; i++) {
        float4 o;
        o.x = silu_f(acc[i][0]); o.y = silu_f(acc[i][1]);
        o.z = silu_f(acc[i][2]); o.w = silu_f(acc[i][3]);
        *(float4*)&ob[(size_t)(m0 + (ty << 2) + i) * LPIX + n0 + (tx << 2)] = o;
    }
}

// ---------------- launch ----------------
extern "C" void kernel_launch(void* const* d_in, const int* in_sizes, int n_in,
                              void* d_out, int out_size) {
    const float* x      = (const float*)d_in[0];
    const float* bbox   = (const float*)d_in[1];
    // d_in[2] = value_shapes (constant [64,64], hardcoded)
    const float* cv1_w  = (const float*)d_in[3];
    const float* m0c1   = (const float*)d_in[4];
    const float* m0c2   = (const float*)d_in[5];
    const float* m1c1   = (const float*)d_in[6];
    const float* m1c2   = (const float*)d_in[7];
    const float* vw     = (const float*)d_in[8];
    const float* vb     = (const float*)d_in[9];
    const float* ow     = (const float*)d_in[10];
    const float* ob     = (const float*)d_in[11];
    const float* aww    = (const float*)d_in[12];
    const float* awb    = (const float*)d_in[13];
    const float* outw   = (const float*)d_in[14];
    const float* outb   = (const float*)d_in[15];
    const float* cv2w   = (const float*)d_in[16];

    dim3 thr(256);
    k_cv1<<<dim3(64, 8, NBATCH), thr>>>(x, cv1_w);
    k_conv3<<<dim3(64, 4, NBATCH), thr>>>(0, m0c1);
    k_conv3<<<dim3(64, 4, NBATCH), thr>>>(1, m0c2);
    k_conv3<<<dim3(64, 4, NBATCH), thr>>>(2, m1c1);
    k_conv3<<<dim3(64, 4, NBATCH), thr>>>(3, m1c2);
    k_proj<<<dim3(4, 64, NBATCH), thr>>>(0, vw, vb);
    k_proj<<<dim3(1, 64, NBATCH), thr>>>(1, ow, ob);
    k_proj<<<dim3(1, 64, NBATCH), thr>>>(2, aww, awb);
    k_sample<<<(NBATCH * LPIX * 64 + 255) / 256, 256>>>(bbox);
    k_outproj<<<dim3(4, 64, NBATCH), thr>>>(outw, outb);
    k_cv2<<<dim3(64, 8, NBATCH), thr>>>(cv2w, (float*)d_out);
}

// round 3
// speedup vs baseline: 3.1741x; 3.1741x over previous
#include <cuda_runtime.h>
#include <cuda_bf16.h>
#include <cstdint>

#define NB 8
#define LP 4096

// ======================= PTX helpers (baseline ISA only) =======================
__device__ __forceinline__ uint32_t smem_u32(const void* p){
    uint32_t a;
    asm("{ .reg .u64 t; cvta.to.shared.u64 t, %1; cvt.u32.u64 %0, t; }" : "=r"(a) : "l"(p));
    return a;
}
__device__ __forceinline__ void cpa16(uint32_t dst, const void* src, uint32_t nbytes){
    asm volatile("cp.async.cg.shared.global [%0], [%1], 16, %2;"
        :: "r"(dst), "l"(src), "r"(nbytes) : "memory");
}
#define CP_COMMIT() asm volatile("cp.async.commit_group;" ::: "memory")
#define CP_WAIT1()  asm volatile("cp.async.wait_group 1;" ::: "memory")
#define CP_WAIT0()  asm volatile("cp.async.wait_group 0;" ::: "memory")

__device__ __forceinline__ void ldsm4(uint32_t* r, uint32_t a){
    asm volatile("ldmatrix.sync.aligned.m8n8.x4.shared.b16 {%0,%1,%2,%3}, [%4];"
        : "=r"(r[0]), "=r"(r[1]), "=r"(r[2]), "=r"(r[3]) : "r"(a));
}
__device__ __forceinline__ void mma16816(float* c, const uint32_t* a, uint32_t b0, uint32_t b1){
    asm volatile("mma.sync.aligned.m16n8k16.row.col.f32.bf16.bf16.f32 "
        "{%0,%1,%2,%3}, {%4,%5,%6,%7}, {%8,%9}, {%0,%1,%2,%3};"
        : "+f"(c[0]), "+f"(c[1]), "+f"(c[2]), "+f"(c[3])
        : "r"(a[0]), "r"(a[1]), "r"(a[2]), "r"(a[3]), "r"(b0), "r"(b1));
}

// ======================= device scratch =======================
__device__ __nv_bfloat16 g_xah[(size_t)NB*LP*512], g_xal[(size_t)NB*LP*512];
__device__ __nv_bfloat16 g_y0h[(size_t)NB*LP*512], g_y0l[(size_t)NB*LP*512];
__device__ __nv_bfloat16 g_t0h[(size_t)NB*LP*256], g_t0l[(size_t)NB*LP*256];
__device__ __nv_bfloat16 g_b1h[(size_t)NB*LP*256], g_b1l[(size_t)NB*LP*256];
__device__ __nv_bfloat16 g_t1h[(size_t)NB*LP*256], g_t1l[(size_t)NB*LP*256];
__device__ __nv_bfloat16 g_b2h[(size_t)NB*LP*256], g_b2l[(size_t)NB*LP*256];
__device__ float g_value[(size_t)NB*LP*256];
__device__ float g_off [(size_t)NB*LP*64];
__device__ float g_awL [(size_t)NB*LP*32];
__device__ __nv_bfloat16 g_smh[(size_t)NB*LP*256], g_sml[(size_t)NB*LP*256];
__device__ __nv_bfloat16 g_ath[(size_t)NB*LP*256], g_atl[(size_t)NB*LP*256];

__device__ __nv_bfloat16 g_wcv1h[512*512],  g_wcv1l[512*512];
__device__ __nv_bfloat16 g_wc0h[256*2304],  g_wc0l[256*2304];
__device__ __nv_bfloat16 g_wc1h[256*2304],  g_wc1l[256*2304];
__device__ __nv_bfloat16 g_wc2h[256*2304],  g_wc2l[256*2304];
__device__ __nv_bfloat16 g_wc3h[256*2304],  g_wc3l[256*2304];
__device__ __nv_bfloat16 g_wcth[384*256],   g_wctl[384*256];
__device__ float         g_bct[384];
__device__ __nv_bfloat16 g_woh[256*256],    g_wol[256*256];
__device__ __nv_bfloat16 g_wv2h[512*1280],  g_wv2l[512*1280];

__device__ __forceinline__ void split2(float v, __nv_bfloat16& h, __nv_bfloat16& l){
    h = __float2bfloat16(v);
    l = __float2bfloat16(v - __bfloat162float(h));
}
__device__ __forceinline__ float silu_f(float v){ return v / (1.f + __expf(-v)); }
__device__ __forceinline__ uint32_t pack_bf2(float a, float b){
    __nv_bfloat16 ha = __float2bfloat16(a), hb = __float2bfloat16(b);
    return (uint32_t)__bfloat16_as_ushort(ha) | ((uint32_t)__bfloat16_as_ushort(hb) << 16);
}

// ======================= conversion kernels =======================
__global__ void k_cvt_x(const float* __restrict__ x){
    __shared__ float t[32][33];
    int b = blockIdx.z, l0 = blockIdx.x<<5, c0 = blockIdx.y<<5;
    int tx = threadIdx.x, ty = threadIdx.y;
#pragma unroll
    for (int i=0;i<32;i+=8)
        t[ty+i][tx] = x[((size_t)((b<<9)+(c0+ty+i))<<12) + l0 + tx];
    __syncthreads();
#pragma unroll
    for (int i=0;i<32;i+=8){
        float v = t[tx][ty+i];
        size_t o = ((size_t)((b<<12)+(l0+ty+i))<<9) + c0 + tx;
        __nv_bfloat16 h, l2; split2(v, h, l2);
        g_xah[o] = h; g_xal[o] = l2;
    }
}

__global__ void k_cvt_wplain(int which, const float* __restrict__ src){
    size_t n; __nv_bfloat16 *dh, *dl;
    if (which == 0){ n = 512*512;  dh = g_wcv1h; dl = g_wcv1l; }
    else           { n = 512*1280; dh = g_wv2h;  dl = g_wv2l;  }
    size_t i = (size_t)blockIdx.x*256 + threadIdx.x;
    if (i >= n) return;
    __nv_bfloat16 h, l2; split2(src[i], h, l2);
    dh[i] = h; dl[i] = l2;
}

// conv weights: src [o][ic][3][3] -> dst[o][tap*256 + ic]
__global__ void k_cvt_wconv(int which, const float* __restrict__ src){
    __nv_bfloat16 *dh, *dl;
    if (which==0){ dh=g_wc0h; dl=g_wc0l; }
    else if (which==1){ dh=g_wc1h; dl=g_wc1l; }
    else if (which==2){ dh=g_wc2h; dl=g_wc2l; }
    else { dh=g_wc3h; dl=g_wc3l; }
    size_t i = (size_t)blockIdx.x*256 + threadIdx.x;
    if (i >= (size_t)256*2304) return;
    int o = (int)(i / 2304);
    int k = (int)(i - (size_t)o*2304);
    int j = k >> 8, ic = k & 255;
    float v = src[((size_t)o*256 + ic)*9 + j];
    __nv_bfloat16 h, l2; split2(v, h, l2);
    dh[i] = h; dl[i] = l2;
}

// fused projection weights: rows n: [0,256)=value, [256,320)=off, [320,352)=aw, rest zero
__global__ void k_cvt_cat(const float* __restrict__ vw, const float* __restrict__ vb2,
                          const float* __restrict__ ow2, const float* __restrict__ ob2,
                          const float* __restrict__ aw2, const float* __restrict__ ab2){
    size_t i = (size_t)blockIdx.x*256 + threadIdx.x;
    if (i >= (size_t)384*256) return;
    int n = (int)(i >> 8), c = (int)(i & 255);
    float v = 0.f;
    if (n < 256)       v = vw[(size_t)c*256 + n];
    else if (n < 320)  v = ow2[(size_t)c*64 + (n-256)];
    else if (n < 352)  v = aw2[(size_t)c*32 + (n-320)];
    __nv_bfloat16 h, l2; split2(v, h, l2);
    g_wcth[i] = h; g_wctl[i] = l2;
    if (c == 0){
        float bv = 0.f;
        if (n < 256) bv = vb2[n];
        else if (n < 320) bv = ob2[n-256];
        else if (n < 352) bv = ab2[n-320];
        g_bct[n] = bv;
    }
}

__global__ void k_cvt_wout(const float* __restrict__ src){
    size_t i = (size_t)blockIdx.x*256 + threadIdx.x;
    if (i >= (size_t)256*256) return;
    int n = (int)(i >> 8), c = (int)(i & 255);
    __nv_bfloat16 h, l2; split2(src[(size_t)c*256 + n], h, l2);
    g_woh[i] = h; g_wol[i] = l2;
}

// ======================= main GEMM (mma.sync bf16, 3-term fp32 emulation) =======================
// CTA tile 128(m=pixels) x 128(n=outch) x 64(k). 8 warps (2x4). Warp tile 64x32.
#define SMEM_BYTES 131072

__global__ __launch_bounds__(256, 1) void k_gemm(int stage, const float* __restrict__ ebias,
                                                 float* __restrict__ dout)
{
    extern __shared__ char smc[];
    const uint32_t sb = smem_u32(smc);
    const int tid = threadIdx.x;
    const int wid = tid >> 5, lid = tid & 31;
    const int b  = blockIdx.z;
    const int l0 = blockIdx.y << 7;
    const int n0 = blockIdx.x << 7;

    int K;
    const __nv_bfloat16 *wh, *wl;
    switch (stage){
        case 0: K = 512;  wh = g_wcv1h; wl = g_wcv1l; break;
        case 1: K = 2304; wh = g_wc0h;  wl = g_wc0l;  break;
        case 2: K = 2304; wh = g_wc1h;  wl = g_wc1l;  break;
        case 3: K = 2304; wh = g_wc2h;  wl = g_wc2l;  break;
        case 4: K = 2304; wh = g_wc3h;  wl = g_wc3l;  break;
        case 5: K = 256;  wh = g_wcth;  wl = g_wctl;  break;
        case 6: K = 256;  wh = g_woh;   wl = g_wol;   break;
        default:K = 1280; wh = g_wv2h;  wl = g_wv2l;  break;
    }
    const int NC = K >> 6;

    float acc[4][4][4];
#pragma unroll
    for (int i=0;i<4;i++)
#pragma unroll
    for (int j=0;j<4;j++)
#pragma unroll
    for (int e=0;e<4;e++) acc[i][j][e] = 0.f;

    const int wm = wid >> 2, wn = wid & 3;

    auto issue = [&](int cc){
        const int buf = cc & 1;
        const __nv_bfloat16 *ah, *al; int ach, acb, ady = 0, adx = 0; bool acv = false;
        const int k0c = cc << 6;
        if (stage == 0){ ah = g_xah; al = g_xal; ach = 512; acb = k0c; }
        else if (stage <= 4){
            int j = cc >> 2; int jd = j / 3;
            ady = jd - 1; adx = j - jd*3 - 1; acv = true;
            int ic0 = (cc & 3) << 6;
            if (stage == 1){ ah = g_y0h; al = g_y0l; ach = 512; acb = 256 + ic0; }
            else if (stage == 2){ ah = g_t0h; al = g_t0l; ach = 256; acb = ic0; }
            else if (stage == 3){ ah = g_b1h; al = g_b1l; ach = 256; acb = ic0; }
            else { ah = g_t1h; al = g_t1l; ach = 256; acb = ic0; }
        }
        else if (stage == 5){ ah = g_b2h; al = g_b2l; ach = 256; acb = k0c; }
        else if (stage == 6){ ah = g_smh; al = g_sml; ach = 256; acb = k0c; }
        else {
            if (k0c < 512)      { ah = g_y0h; al = g_y0l; ach = 512; acb = k0c; }
            else if (k0c < 768) { ah = g_b1h; al = g_b1l; ach = 256; acb = k0c - 512; }
            else if (k0c < 1024){ ah = g_b2h; al = g_b2l; ach = 256; acb = k0c - 768; }
            else                { ah = g_ath; al = g_atl; ach = 256; acb = k0c - 1024; }
        }
        uint32_t base = sb + (uint32_t)buf * 65536u;
#pragma unroll
        for (int it4 = 0; it4 < 4; it4++){
            int it = tid + (it4 << 8);     // 0..1023
            int m = it >> 3, u = it & 7;   // row, 16B unit (8 bf16)
            uint32_t so = (uint32_t)it << 4;
            uint32_t sw = so ^ ((so >> 3) & 0x70);
            size_t off = 0; uint32_t nb = 16;
            if (acv){
                int p = l0 + m;
                int sy = (p >> 6) + ady, sx = (p & 63) + adx;
                if ((unsigned)sy < 64u && (unsigned)sx < 64u)
                    off = (size_t)((b<<12) + (sy<<6) + sx) * ach + acb + (u<<3);
                else nb = 0;
            } else {
                off = (size_t)((b<<12) + l0 + m) * ach + acb + (u<<3);
            }
            cpa16(base + sw,          ah + off, nb);
            cpa16(base + 16384 + sw,  al + off, nb);
            size_t woff = (size_t)(n0 + m) * K + k0c + (u<<3);
            cpa16(base + 32768 + sw,  wh + woff, 16);
            cpa16(base + 49152 + sw,  wl + woff, 16);
        }
        CP_COMMIT();
    };

    issue(0);
    for (int cc = 0; cc < NC; cc++){
        if (cc + 1 < NC){ issue(cc + 1); CP_WAIT1(); } else { CP_WAIT0(); }
        __syncthreads();
        uint32_t ua = sb + (uint32_t)(cc & 1) * 65536u;
        const int mat = lid >> 3, r8 = lid & 7;
#pragma unroll
        for (int ks = 0; ks < 4; ks++){
            uint32_t ahf[4][4], alf[4][4], bhf[2][4], blf[2][4];
#pragma unroll
            for (int mi = 0; mi < 4; mi++){
                int row = (wm << 6) + (mi << 4) + ((mat & 1) << 3) + r8;
                int kb  = (ks << 5) + ((mat >> 1) << 4);
                uint32_t o = ((uint32_t)row << 7) + kb;
                uint32_t swo = o ^ ((o >> 3) & 0x70);
                ldsm4(ahf[mi], ua + swo);
                ldsm4(alf[mi], ua + 16384 + swo);
            }
#pragma unroll
            for (int bi = 0; bi < 2; bi++){
                int row = (wn << 5) + (bi << 4) + ((mat >> 1) << 3) + r8;
                int kb  = (ks << 5) + ((mat & 1) << 4);
                uint32_t o = ((uint32_t)row << 7) + kb;
                uint32_t swo = o ^ ((o >> 3) & 0x70);
                ldsm4(bhf[bi], ua + 32768 + swo);
                ldsm4(blf[bi], ua + 49152 + swo);
            }
#pragma unroll
            for (int mi = 0; mi < 4; mi++)
#pragma unroll
            for (int ni = 0; ni < 4; ni++){
                uint32_t b0h = bhf[ni >> 1][(ni & 1) << 1], b1h = bhf[ni >> 1][((ni & 1) << 1) + 1];
                uint32_t b0l = blf[ni >> 1][(ni & 1) << 1], b1l = blf[ni >> 1][((ni & 1) << 1) + 1];
                mma16816(acc[mi][ni], ahf[mi], b0h, b1h);
                mma16816(acc[mi][ni], ahf[mi], b0l, b1l);
                mma16816(acc[mi][ni], alf[mi], b0h, b1h);
            }
        }
        __syncthreads();
    }

    // ---------------- epilogue ----------------
    const int qr = lid >> 2;
    const int qc = (lid & 3) << 1;
#pragma unroll
    for (int mi = 0; mi < 4; mi++){
#pragma unroll
        for (int ni = 0; ni < 4; ni++){
            float* c = acc[mi][ni];
            int ch = (wn << 5) + (ni << 3) + qc;       // 0..127 local col (even)
            int r0 = (wm << 6) + (mi << 4) + qr;
            int r1 = r0 + 8;

            if (stage <= 4){
                __nv_bfloat16 *dh, *dl2; int OC;
                if (stage == 0){ dh = g_y0h; dl2 = g_y0l; OC = 512; }
                else if (stage == 1){ dh = g_t0h; dl2 = g_t0l; OC = 256; }
                else if (stage == 2){ dh = g_b1h; dl2 = g_b1l; OC = 256; }
                else if (stage == 3){ dh = g_t1h; dl2 = g_t1l; OC = 256; }
                else { dh = g_b2h; dl2 = g_b2l; OC = 256; }
#pragma unroll
                for (int h2 = 0; h2 < 2; h2++){
                    int r = h2 ? r1 : r0;
                    float v0 = silu_f(c[2*h2]), v1 = silu_f(c[2*h2+1]);
                    __nv_bfloat16 h0, q0, h1, q1;
                    split2(v0, h0, q0); split2(v1, h1, q1);
                    size_t o = ((size_t)((b<<12) + l0 + r)) * OC + n0 + ch;
                    *(uint32_t*)&dh [o] = (uint32_t)__bfloat16_as_ushort(h0) | ((uint32_t)__bfloat16_as_ushort(h1) << 16);
                    *(uint32_t*)&dl2[o] = (uint32_t)__bfloat16_as_ushort(q0) | ((uint32_t)__bfloat16_as_ushort(q1) << 16);
                }
            } else if (stage == 5){
#pragma unroll
                for (int h2 = 0; h2 < 2; h2++){
                    int r = h2 ? r1 : r0;
                    size_t bl = (size_t)(b<<12) + l0 + r;
#pragma unroll
                    for (int e = 0; e < 2; e++){
                        int ng = n0 + ch + e;
                        float v = c[2*h2 + e] + g_bct[ng];
                        if (ng < 256)      g_value[bl*256 + ng] = v;
                        else if (ng < 320) g_off [bl*64 + (ng - 256)] = v;
                        else if (ng < 352) g_awL [bl*32 + (ng - 320)] = v;
                    }
                }
            } else if (stage == 6){
#pragma unroll
                for (int h2 = 0; h2 < 2; h2++){
                    int r = h2 ? r1 : r0;
                    float v0 = c[2*h2]     + ebias[n0 + ch];
                    float v1 = c[2*h2 + 1] + ebias[n0 + ch + 1];
                    __nv_bfloat16 h0, q0, h1, q1;
                    split2(v0, h0, q0); split2(v1, h1, q1);
                    size_t o = ((size_t)((b<<12) + l0 + r)) * 256 + n0 + ch;
                    *(uint32_t*)&g_ath[o] = (uint32_t)__bfloat16_as_ushort(h0) | ((uint32_t)__bfloat16_as_ushort(h1) << 16);
                    *(uint32_t*)&g_atl[o] = (uint32_t)__bfloat16_as_ushort(q0) | ((uint32_t)__bfloat16_as_ushort(q1) << 16);
                }
            } else {
#pragma unroll
                for (int h2 = 0; h2 < 2; h2++){
                    int r = h2 ? r1 : r0;
#pragma unroll
                    for (int e = 0; e < 2; e++){
                        float v = silu_f(c[2*h2 + e]);
                        dout[((size_t)((b << 9) + n0 + ch + e) << 12) + l0 + r] = v;
                    }
                }
            }
        }
    }
}

// ======================= deformable sampling =======================
__global__ void k_sample(const float* __restrict__ bbox){
    int g = blockIdx.x * blockDim.x + threadIdx.x;
    if (g >= NB * LP * 64) return;
    int d4 = g & 7;
    int hd = (g >> 3) & 7;
    int l  = (g >> 6) & 4095;
    int b  = g >> 18;
    size_t bl = (size_t)b * LP + l;
    float bx = bbox[bl*2 + 0];
    float by = bbox[bl*2 + 1];
    const float* op = g_off + bl*64 + hd*8;
    const float* ap = g_awL + bl*32 + hd*4;

    float a0 = ap[0], a1 = ap[1], a2 = ap[2], a3 = ap[3];
    float mx = fmaxf(fmaxf(a0, a1), fmaxf(a2, a3));
    float e0 = __expf(a0 - mx), e1 = __expf(a1 - mx), e2 = __expf(a2 - mx), e3 = __expf(a3 - mx);
    float inv = 1.f / (e0 + e1 + e2 + e3);
    float wp[4] = {e0*inv, e1*inv, e2*inv, e3*inv};

    const float* vb = g_value + ((size_t)b * LP) * 256 + hd*32 + (d4 << 2);
    float4 acc = make_float4(0.f, 0.f, 0.f, 0.f);
#pragma unroll
    for (int p = 0; p < 4; p++){
        float lx = bx + op[p*2 + 0] * 0.015625f;
        float ly = by + op[p*2 + 1] * 0.015625f;
        float gx = lx * 64.f - 0.5f;
        float gy = ly * 64.f - 0.5f;
        float fx = floorf(gx), fy = floorf(gy);
        float wx1 = gx - fx, wy1 = gy - fy;
        float wx0 = 1.f - wx1, wy0 = 1.f - wy1;
        int ix = (int)fx, iy = (int)fy;
        float awp = wp[p];
#pragma unroll
        for (int c2 = 0; c2 < 4; c2++){
            int cx = ix + (c2 & 1);
            int cy = iy + (c2 >> 1);
            if ((unsigned)cx < 64u && (unsigned)cy < 64u){
                float wgt = awp * ((c2 & 1) ? wx1 : wx0) * ((c2 >> 1) ? wy1 : wy0);
                float4 v = *(const float4*)&vb[(size_t)((cy << 6) + cx) * 256];
                acc.x += wgt * v.x; acc.y += wgt * v.y;
                acc.z += wgt * v.z; acc.w += wgt * v.w;
            }
        }
    }
    size_t o = bl*256 + hd*32 + (d4 << 2);
    __nv_bfloat16 h, l2;
    split2(acc.x, h, l2); g_smh[o+0] = h; g_sml[o+0] = l2;
    split2(acc.y, h, l2); g_smh[o+1] = h; g_sml[o+1] = l2;
    split2(acc.z, h, l2); g_smh[o+2] = h; g_sml[o+2] = l2;
    split2(acc.w, h, l2); g_smh[o+3] = h; g_sml[o+3] = l2;
}

// ======================= launch =======================
extern "C" void kernel_launch(void* const* d_in, const int* in_sizes, int n_in,
                              void* d_out, int out_size) {
    const float* x    = (const float*)d_in[0];
    const float* bbox = (const float*)d_in[1];
    const float* cv1w = (const float*)d_in[3];
    const float* m0c1 = (const float*)d_in[4];
    const float* m0c2 = (const float*)d_in[5];
    const float* m1c1 = (const float*)d_in[6];
    const float* m1c2 = (const float*)d_in[7];
    const float* vw   = (const float*)d_in[8];
    const float* vb   = (const float*)d_in[9];
    const float* ow   = (const float*)d_in[10];
    const float* ob   = (const float*)d_in[11];
    const float* aww  = (const float*)d_in[12];
    const float* awb  = (const float*)d_in[13];
    const float* outw = (const float*)d_in[14];
    const float* outb = (const float*)d_in[15];
    const float* cv2w = (const float*)d_in[16];

    cudaFuncSetAttribute(k_gemm, cudaFuncAttributeMaxDynamicSharedMemorySize, SMEM_BYTES);

    k_cvt_x<<<dim3(128, 16, NB), dim3(32, 8)>>>(x);
    k_cvt_wplain<<<1024, 256>>>(0, cv1w);
    k_cvt_wplain<<<2560, 256>>>(1, cv2w);
    k_cvt_wconv<<<2304, 256>>>(0, m0c1);
    k_cvt_wconv<<<2304, 256>>>(1, m0c2);
    k_cvt_wconv<<<2304, 256>>>(2, m1c1);
    k_cvt_wconv<<<2304, 256>>>(3, m1c2);
    k_cvt_cat<<<384, 256>>>(vw, vb, ow, ob, aww, awb);
    k_cvt_wout<<<256, 256>>>(outw);

    k_gemm<<<dim3(4, 32, NB), 256, SMEM_BYTES>>>(0, nullptr, nullptr);   // cv1
    k_gemm<<<dim3(2, 32, NB), 256, SMEM_BYTES>>>(1, nullptr, nullptr);   // m0_cv1
    k_gemm<<<dim3(2, 32, NB), 256, SMEM_BYTES>>>(2, nullptr, nullptr);   // m0_cv2
    k_gemm<<<dim3(2, 32, NB), 256, SMEM_BYTES>>>(3, nullptr, nullptr);   // m1_cv1
    k_gemm<<<dim3(2, 32, NB), 256, SMEM_BYTES>>>(4, nullptr, nullptr);   // m1_cv2
    k_gemm<<<dim3(3, 32, NB), 256, SMEM_BYTES>>>(5, nullptr, nullptr);   // fused projections
    k_sample<<<(NB * LP * 64 + 255) / 256, 256>>>(bbox);
    k_gemm<<<dim3(2, 32, NB), 256, SMEM_BYTES>>>(6, outb, nullptr);      // out projection
    k_gemm<<<dim3(4, 32, NB), 256, SMEM_BYTES>>>(7, nullptr, (float*)d_out); // cv2
}

// round 4
// speedup vs baseline: 3.3934x; 1.0691x over previous
#include <cuda_runtime.h>
#include <cuda_bf16.h>
#include <cstdint>

#define NB 8
#define LP 4096

// ======================= PTX helpers (baseline ISA only) =======================
__device__ __forceinline__ uint32_t smem_u32(const void* p){
    uint32_t a;
    asm("{ .reg .u64 t; cvta.to.shared.u64 t, %1; cvt.u32.u64 %0, t; }" : "=r"(a) : "l"(p));
    return a;
}
__device__ __forceinline__ void cpa16(uint32_t dst, const void* src, uint32_t nbytes){
    asm volatile("cp.async.cg.shared.global [%0], [%1], 16, %2;"
        :: "r"(dst), "l"(src), "r"(nbytes) : "memory");
}
#define CP_COMMIT() asm volatile("cp.async.commit_group;" ::: "memory")
#define CP_WAIT2()  asm volatile("cp.async.wait_group 2;" ::: "memory")

__device__ __forceinline__ void ldsm4(uint32_t* r, uint32_t a){
    asm volatile("ldmatrix.sync.aligned.m8n8.x4.shared.b16 {%0,%1,%2,%3}, [%4];"
        : "=r"(r[0]), "=r"(r[1]), "=r"(r[2]), "=r"(r[3]) : "r"(a));
}
__device__ __forceinline__ void mma16816(float* c, const uint32_t* a, uint32_t b0, uint32_t b1){
    asm volatile("mma.sync.aligned.m16n8k16.row.col.f32.bf16.bf16.f32 "
        "{%0,%1,%2,%3}, {%4,%5,%6,%7}, {%8,%9}, {%0,%1,%2,%3};"
        : "+f"(c[0]), "+f"(c[1]), "+f"(c[2]), "+f"(c[3])
        : "r"(a[0]), "r"(a[1]), "r"(a[2]), "r"(a[3]), "r"(b0), "r"(b1));
}

// ======================= device scratch =======================
__device__ __nv_bfloat16 g_xah[(size_t)NB*LP*512], g_xal[(size_t)NB*LP*512];
__device__ __nv_bfloat16 g_y0h[(size_t)NB*LP*512], g_y0l[(size_t)NB*LP*512];
__device__ __nv_bfloat16 g_t0h[(size_t)NB*LP*256], g_t0l[(size_t)NB*LP*256];
__device__ __nv_bfloat16 g_b1h[(size_t)NB*LP*256], g_b1l[(size_t)NB*LP*256];
__device__ __nv_bfloat16 g_t1h[(size_t)NB*LP*256], g_t1l[(size_t)NB*LP*256];
__device__ __nv_bfloat16 g_b2h[(size_t)NB*LP*256], g_b2l[(size_t)NB*LP*256];
__device__ float g_value[(size_t)NB*LP*256];
__device__ float g_off [(size_t)NB*LP*64];
__device__ float g_awL [(size_t)NB*LP*32];
__device__ __nv_bfloat16 g_smh[(size_t)NB*LP*256], g_sml[(size_t)NB*LP*256];
__device__ __nv_bfloat16 g_ath[(size_t)NB*LP*256], g_atl[(size_t)NB*LP*256];

__device__ __nv_bfloat16 g_wcv1h[512*512],  g_wcv1l[512*512];
__device__ __nv_bfloat16 g_wc0h[256*2304],  g_wc0l[256*2304];
__device__ __nv_bfloat16 g_wc1h[256*2304],  g_wc1l[256*2304];
__device__ __nv_bfloat16 g_wc2h[256*2304],  g_wc2l[256*2304];
__device__ __nv_bfloat16 g_wc3h[256*2304],  g_wc3l[256*2304];
__device__ __nv_bfloat16 g_wcth[384*256],   g_wctl[384*256];
__device__ float         g_bct[384];
__device__ __nv_bfloat16 g_woh[256*256],    g_wol[256*256];
__device__ __nv_bfloat16 g_wv2h[512*1280],  g_wv2l[512*1280];

__device__ __forceinline__ void split2(float v, __nv_bfloat16& h, __nv_bfloat16& l){
    h = __float2bfloat16(v);
    l = __float2bfloat16(v - __bfloat162float(h));
}
__device__ __forceinline__ float silu_f(float v){ return v / (1.f + __expf(-v)); }

// ======================= conversion kernels =======================
__global__ void k_cvt_x(const float* __restrict__ x){
    __shared__ float t[32][33];
    int b = blockIdx.z, l0 = blockIdx.x<<5, c0 = blockIdx.y<<5;
    int tx = threadIdx.x, ty = threadIdx.y;
#pragma unroll
    for (int i=0;i<32;i+=8)
        t[ty+i][tx] = x[((size_t)((b<<9)+(c0+ty+i))<<12) + l0 + tx];
    __syncthreads();
#pragma unroll
    for (int i=0;i<32;i+=8){
        float v = t[tx][ty+i];
        size_t o = ((size_t)((b<<12)+(l0+ty+i))<<9) + c0 + tx;
        __nv_bfloat16 h, l2; split2(v, h, l2);
        g_xah[o] = h; g_xal[o] = l2;
    }
}

// all weight conversions in one launch; branch on blockIdx.y
__global__ void k_cvt_w(const float* __restrict__ cv1w, const float* __restrict__ cv2w,
                        const float* __restrict__ c0, const float* __restrict__ c1,
                        const float* __restrict__ c2, const float* __restrict__ c3,
                        const float* __restrict__ vw, const float* __restrict__ vb2,
                        const float* __restrict__ ow2, const float* __restrict__ ob2,
                        const float* __restrict__ aw2, const float* __restrict__ ab2,
                        const float* __restrict__ outw){
    int which = blockIdx.y;
    size_t i = (size_t)blockIdx.x*256 + threadIdx.x;
    if (which == 0){
        if (i >= (size_t)512*512) return;
        __nv_bfloat16 h, l2; split2(cv1w[i], h, l2);
        g_wcv1h[i] = h; g_wcv1l[i] = l2;
    } else if (which == 1){
        if (i >= (size_t)512*1280) return;
        __nv_bfloat16 h, l2; split2(cv2w[i], h, l2);
        g_wv2h[i] = h; g_wv2l[i] = l2;
    } else if (which <= 5){
        if (i >= (size_t)256*2304) return;
        const float* src = (which==2)?c0:(which==3)?c1:(which==4)?c2:c3;
        __nv_bfloat16 *dh = (which==2)?g_wc0h:(which==3)?g_wc1h:(which==4)?g_wc2h:g_wc3h;
        __nv_bfloat16 *dl = (which==2)?g_wc0l:(which==3)?g_wc1l:(which==4)?g_wc2l:g_wc3l;
        int o = (int)(i / 2304);
        int k = (int)(i - (size_t)o*2304);
        int j = k >> 8, ic = k & 255;
        __nv_bfloat16 h, l2; split2(src[((size_t)o*256 + ic)*9 + j], h, l2);
        dh[i] = h; dl[i] = l2;
    } else if (which == 6){
        if (i >= (size_t)384*256) return;
        int n = (int)(i >> 8), c = (int)(i & 255);
        float v = 0.f;
        if (n < 256)       v = vw[(size_t)c*256 + n];
        else if (n < 320)  v = ow2[(size_t)c*64 + (n-256)];
        else if (n < 352)  v = aw2[(size_t)c*32 + (n-320)];
        __nv_bfloat16 h, l2; split2(v, h, l2);
        g_wcth[i] = h; g_wctl[i] = l2;
        if (c == 0){
            float bv = 0.f;
            if (n < 256) bv = vb2[n];
            else if (n < 320) bv = ob2[n-256];
            else if (n < 352) bv = ab2[n-320];
            g_bct[n] = bv;
        }
    } else {
        if (i >= (size_t)256*256) return;
        int n = (int)(i >> 8), c = (int)(i & 255);
        __nv_bfloat16 h, l2; split2(outw[(size_t)c*256 + n], h, l2);
        g_woh[i] = h; g_wol[i] = l2;
    }
}

// ======================= main GEMM (mma.sync bf16, 3-term fp32 emulation) =======================
// CTA tile 128(m) x 128(n) x 32(k). 8 warps (2x4), warp tile 64x32.
// SMEM: 3 ring buffers x 32KB (Ah 8K | Al 8K | Bh 8K | Bl 8K). 2 CTAs/SM.
#define SMEM_BYTES (3*32768)

__global__ __launch_bounds__(256, 2) void k_gemm(int stage, const float* __restrict__ ebias,
                                                 float* __restrict__ dout)
{
    extern __shared__ char smc[];
    const uint32_t sb = smem_u32(smc);
    const int tid = threadIdx.x;
    const int wid = tid >> 5, lid = tid & 31;
    const int b  = blockIdx.z;
    const int l0 = blockIdx.y << 7;
    const int n0 = blockIdx.x << 7;

    int K;
    const __nv_bfloat16 *wh, *wl;
    switch (stage){
        case 0: K = 512;  wh = g_wcv1h; wl = g_wcv1l; break;
        case 1: K = 2304; wh = g_wc0h;  wl = g_wc0l;  break;
        case 2: K = 2304; wh = g_wc1h;  wl = g_wc1l;  break;
        case 3: K = 2304; wh = g_wc2h;  wl = g_wc2l;  break;
        case 4: K = 2304; wh = g_wc3h;  wl = g_wc3l;  break;
        case 5: K = 256;  wh = g_wcth;  wl = g_wctl;  break;
        case 6: K = 256;  wh = g_woh;   wl = g_wol;   break;
        default:K = 1280; wh = g_wv2h;  wl = g_wv2l;  break;
    }
    const int NC = K >> 5;          // k32 chunks

    float acc[4][4][4];
#pragma unroll
    for (int i=0;i<4;i++)
#pragma unroll
    for (int j=0;j<4;j++)
#pragma unroll
    for (int e=0;e<4;e++) acc[i][j][e] = 0.f;

    const int wm = wid >> 2, wn = wid & 3;

    auto issue = [&](int cc){
        const __nv_bfloat16 *ah, *al; int ach, acb, ady = 0, adx = 0; bool acv = false;
        const int k0c = cc << 5;
        if (stage == 0){ ah = g_xah; al = g_xal; ach = 512; acb = k0c; }
        else if (stage <= 4){
            int j = cc >> 3; int jd = j / 3;
            ady = jd - 1; adx = j - jd*3 - 1; acv = true;
            int ic0 = (cc & 7) << 5;
            if (stage == 1){ ah = g_y0h; al = g_y0l; ach = 512; acb = 256 + ic0; }
            else if (stage == 2){ ah = g_t0h; al = g_t0l; ach = 256; acb = ic0; }
            else if (stage == 3){ ah = g_b1h; al = g_b1l; ach = 256; acb = ic0; }
            else { ah = g_t1h; al = g_t1l; ach = 256; acb = ic0; }
        }
        else if (stage == 5){ ah = g_b2h; al = g_b2l; ach = 256; acb = k0c; }
        else if (stage == 6){ ah = g_smh; al = g_sml; ach = 256; acb = k0c; }
        else {
            if (k0c < 512)      { ah = g_y0h; al = g_y0l; ach = 512; acb = k0c; }
            else if (k0c < 768) { ah = g_b1h; al = g_b1l; ach = 256; acb = k0c - 512; }
            else if (k0c < 1024){ ah = g_b2h; al = g_b2l; ach = 256; acb = k0c - 768; }
            else                { ah = g_ath; al = g_atl; ach = 256; acb = k0c - 1024; }
        }
        uint32_t base = sb + (uint32_t)(cc % 3) * 32768u;
#pragma unroll
        for (int it2 = 0; it2 < 2; it2++){
            int it = tid + (it2 << 8);     // 0..511
            int m = it >> 2, u = it & 3;   // row, 16B unit (8 bf16)
            uint32_t so = (uint32_t)it << 4;
            uint32_t sw = so ^ ((so >> 2) & 0x30);
            size_t off = 0; uint32_t nb = 16;
            if (acv){
                int p = l0 + m;
                int sy = (p >> 6) + ady, sx = (p & 63) + adx;
                if ((unsigned)sy < 64u && (unsigned)sx < 64u)
                    off = (size_t)((b<<12) + (sy<<6) + sx) * ach + acb + (u<<3);
                else nb = 0;
            } else {
                off = (size_t)((b<<12) + l0 + m) * ach + acb + (u<<3);
            }
            cpa16(base + sw,          ah + off, nb);
            cpa16(base + 8192 + sw,   al + off, nb);
            size_t woff = (size_t)(n0 + m) * K + k0c + (u<<3);
            cpa16(base + 16384 + sw,  wh + woff, 16);
            cpa16(base + 24576 + sw,  wl + woff, 16);
        }
        CP_COMMIT();
    };

    issue(0);
    issue(1);
    for (int cc = 0; cc < NC; cc++){
        if (cc + 2 < NC) issue(cc + 2); else CP_COMMIT();
        CP_WAIT2();
        __syncthreads();
        uint32_t ua = sb + (uint32_t)(cc % 3) * 32768u;
        const int mat = lid >> 3, r8 = lid & 7;
#pragma unroll
        for (int ks = 0; ks < 2; ks++){
            uint32_t bh[2][4], blf[2][4], af[4][4];
#pragma unroll
            for (int bi = 0; bi < 2; bi++){
                int row = (wn << 5) + (bi << 4) + ((mat >> 1) << 3) + r8;
                uint32_t o = ((uint32_t)row << 6) + (ks << 5) + ((mat & 1) << 4);
                uint32_t swo = o ^ ((o >> 2) & 0x30);
                ldsm4(bh[bi],  ua + 16384 + swo);
                ldsm4(blf[bi], ua + 24576 + swo);
            }
#pragma unroll
            for (int mi = 0; mi < 4; mi++){
                int row = (wm << 6) + (mi << 4) + ((mat & 1) << 3) + r8;
                uint32_t o = ((uint32_t)row << 6) + (ks << 5) + ((mat >> 1) << 4);
                uint32_t swo = o ^ ((o >> 2) & 0x30);
                ldsm4(af[mi], ua + swo);
            }
#pragma unroll
            for (int mi = 0; mi < 4; mi++)
#pragma unroll
            for (int ni = 0; ni < 4; ni++){
                uint32_t b0h = bh[ni >> 1][(ni & 1) << 1],  b1h = bh[ni >> 1][((ni & 1) << 1) + 1];
                uint32_t b0l = blf[ni >> 1][(ni & 1) << 1], b1l = blf[ni >> 1][((ni & 1) << 1) + 1];
                mma16816(acc[mi][ni], af[mi], b0h, b1h);
                mma16816(acc[mi][ni], af[mi], b0l, b1l);
            }
#pragma unroll
            for (int mi = 0; mi < 4; mi++){
                int row = (wm << 6) + (mi << 4) + ((mat & 1) << 3) + r8;
                uint32_t o = ((uint32_t)row << 6) + (ks << 5) + ((mat >> 1) << 4);
                uint32_t swo = o ^ ((o >> 2) & 0x30);
                ldsm4(af[mi], ua + 8192 + swo);
            }
#pragma unroll
            for (int mi = 0; mi < 4; mi++)
#pragma unroll
            for (int ni = 0; ni < 4; ni++){
                uint32_t b0h = bh[ni >> 1][(ni & 1) << 1], b1h = bh[ni >> 1][((ni & 1) << 1) + 1];
                mma16816(acc[mi][ni], af[mi], b0h, b1h);
            }
        }
        __syncthreads();
    }

    // ---------------- epilogue ----------------
    const int qr = lid >> 2;
    const int qc = (lid & 3) << 1;
#pragma unroll
    for (int mi = 0; mi < 4; mi++){
#pragma unroll
        for (int ni = 0; ni < 4; ni++){
            float* c = acc[mi][ni];
            int ch = (wn << 5) + (ni << 3) + qc;
            int r0 = (wm << 6) + (mi << 4) + qr;
            int r1 = r0 + 8;

            if (stage <= 4){
                __nv_bfloat16 *dh, *dl2; int OC;
                if (stage == 0){ dh = g_y0h; dl2 = g_y0l; OC = 512; }
                else if (stage == 1){ dh = g_t0h; dl2 = g_t0l; OC = 256; }
                else if (stage == 2){ dh = g_b1h; dl2 = g_b1l; OC = 256; }
                else if (stage == 3){ dh = g_t1h; dl2 = g_t1l; OC = 256; }
                else { dh = g_b2h; dl2 = g_b2l; OC = 256; }
#pragma unroll
                for (int h2 = 0; h2 < 2; h2++){
                    int r = h2 ? r1 : r0;
                    float v0 = silu_f(c[2*h2]), v1 = silu_f(c[2*h2+1]);
                    __nv_bfloat16 h0, q0, h1, q1;
                    split2(v0, h0, q0); split2(v1, h1, q1);
                    size_t o = ((size_t)((b<<12) + l0 + r)) * OC + n0 + ch;
                    *(uint32_t*)&dh [o] = (uint32_t)__bfloat16_as_ushort(h0) | ((uint32_t)__bfloat16_as_ushort(h1) << 16);
                    *(uint32_t*)&dl2[o] = (uint32_t)__bfloat16_as_ushort(q0) | ((uint32_t)__bfloat16_as_ushort(q1) << 16);
                }
            } else if (stage == 5){
#pragma unroll
                for (int h2 = 0; h2 < 2; h2++){
                    int r = h2 ? r1 : r0;
                    size_t bl = (size_t)(b<<12) + l0 + r;
#pragma unroll
                    for (int e = 0; e < 2; e++){
                        int ng = n0 + ch + e;
                        float v = c[2*h2 + e] + g_bct[ng];
                        if (ng < 256)      g_value[bl*256 + ng] = v;
                        else if (ng < 320) g_off [bl*64 + (ng - 256)] = v;
                        else if (ng < 352) g_awL [bl*32 + (ng - 320)] = v;
                    }
                }
            } else if (stage == 6){
#pragma unroll
                for (int h2 = 0; h2 < 2; h2++){
                    int r = h2 ? r1 : r0;
                    float v0 = c[2*h2]     + ebias[n0 + ch];
                    float v1 = c[2*h2 + 1] + ebias[n0 + ch + 1];
                    __nv_bfloat16 h0, q0, h1, q1;
                    split2(v0, h0, q0); split2(v1, h1, q1);
                    size_t o = ((size_t)((b<<12) + l0 + r)) * 256 + n0 + ch;
                    *(uint32_t*)&g_ath[o] = (uint32_t)__bfloat16_as_ushort(h0) | ((uint32_t)__bfloat16_as_ushort(h1) << 16);
                    *(uint32_t*)&g_atl[o] = (uint32_t)__bfloat16_as_ushort(q0) | ((uint32_t)__bfloat16_as_ushort(q1) << 16);
                }
            } else {
#pragma unroll
                for (int h2 = 0; h2 < 2; h2++){
                    int r = h2 ? r1 : r0;
#pragma unroll
                    for (int e = 0; e < 2; e++){
                        float v = silu_f(c[2*h2 + e]);
                        dout[((size_t)((b << 9) + n0 + ch + e) << 12) + l0 + r] = v;
                    }
                }
            }
        }
    }
}

// ======================= deformable sampling =======================
__global__ void k_sample(const float* __restrict__ bbox){
    int g = blockIdx.x * blockDim.x + threadIdx.x;
    if (g >= NB * LP * 64) return;
    int d4 = g & 7;
    int hd = (g >> 3) & 7;
    int l  = (g >> 6) & 4095;
    int b  = g >> 18;
    size_t bl = (size_t)b * LP + l;
    float bx = bbox[bl*2 + 0];
    float by = bbox[bl*2 + 1];
    const float* op = g_off + bl*64 + hd*8;
    const float* ap = g_awL + bl*32 + hd*4;

    float a0 = ap[0], a1 = ap[1], a2 = ap[2], a3 = ap[3];
    float mx = fmaxf(fmaxf(a0, a1), fmaxf(a2, a3));
    float e0 = __expf(a0 - mx), e1 = __expf(a1 - mx), e2 = __expf(a2 - mx), e3 = __expf(a3 - mx);
    float inv = 1.f / (e0 + e1 + e2 + e3);
    float wp[4] = {e0*inv, e1*inv, e2*inv, e3*inv};

    const float* vb = g_value + ((size_t)b * LP) * 256 + hd*32 + (d4 << 2);
    float4 acc = make_float4(0.f, 0.f, 0.f, 0.f);
#pragma unroll
    for (int p = 0; p < 4; p++){
        float lx = bx + op[p*2 + 0] * 0.015625f;
        float ly = by + op[p*2 + 1] * 0.015625f;
        float gx = lx * 64.f - 0.5f;
        float gy = ly * 64.f - 0.5f;
        float fx = floorf(gx), fy = floorf(gy);
        float wx1 = gx - fx, wy1 = gy - fy;
        float wx0 = 1.f - wx1, wy0 = 1.f - wy1;
        int ix = (int)fx, iy = (int)fy;
        float awp = wp[p];
#pragma unroll
        for (int c2 = 0; c2 < 4; c2++){
            int cx = ix + (c2 & 1);
            int cy = iy + (c2 >> 1);
            if ((unsigned)cx < 64u && (unsigned)cy < 64u){
                float wgt = awp * ((c2 & 1) ? wx1 : wx0) * ((c2 >> 1) ? wy1 : wy0);
                float4 v = *(const float4*)&vb[(size_t)((cy << 6) + cx) * 256];
                acc.x += wgt * v.x; acc.y += wgt * v.y;
                acc.z += wgt * v.z; acc.w += wgt * v.w;
            }
        }
    }
    size_t o = bl*256 + hd*32 + (d4 << 2);
    __nv_bfloat16 h, l2;
    split2(acc.x, h, l2); g_smh[o+0] = h; g_sml[o+0] = l2;
    split2(acc.y, h, l2); g_smh[o+1] = h; g_sml[o+1] = l2;
    split2(acc.z, h, l2); g_smh[o+2] = h; g_sml[o+2] = l2;
    split2(acc.w, h, l2); g_smh[o+3] = h; g_sml[o+3] = l2;
}

// ======================= launch =======================
extern "C" void kernel_launch(void* const* d_in, const int* in_sizes, int n_in,
                              void* d_out, int out_size) {
    const float* x    = (const float*)d_in[0];
    const float* bbox = (const float*)d_in[1];
    const float* cv1w = (const float*)d_in[3];
    const float* m0c1 = (const float*)d_in[4];
    const float* m0c2 = (const float*)d_in[5];
    const float* m1c1 = (const float*)d_in[6];
    const float* m1c2 = (const float*)d_in[7];
    const float* vw   = (const float*)d_in[8];
    const float* vb   = (const float*)d_in[9];
    const float* ow   = (const float*)d_in[10];
    const float* ob   = (const float*)d_in[11];
    const float* aww  = (const float*)d_in[12];
    const float* awb  = (const float*)d_in[13];
    const float* outw = (const float*)d_in[14];
    const float* outb = (const float*)d_in[15];
    const float* cv2w = (const float*)d_in[16];

    cudaFuncSetAttribute(k_gemm, cudaFuncAttributeMaxDynamicSharedMemorySize, SMEM_BYTES);

    k_cvt_x<<<dim3(128, 16, NB), dim3(32, 8)>>>(x);
    k_cvt_w<<<dim3(2560, 8), 256>>>(cv1w, cv2w, m0c1, m0c2, m1c1, m1c2,
                                    vw, vb, ow, ob, aww, awb, outw);

    k_gemm<<<dim3(4, 32, NB), 256, SMEM_BYTES>>>(0, nullptr, nullptr);   // cv1
    k_gemm<<<dim3(2, 32, NB), 256, SMEM_BYTES>>>(1, nullptr, nullptr);   // m0_cv1
    k_gemm<<<dim3(2, 32, NB), 256, SMEM_BYTES>>>(2, nullptr, nullptr);   // m0_cv2
    k_gemm<<<dim3(2, 32, NB), 256, SMEM_BYTES>>>(3, nullptr, nullptr);   // m1_cv1
    k_gemm<<<dim3(2, 32, NB), 256, SMEM_BYTES>>>(4, nullptr, nullptr);   // m1_cv2
    k_gemm<<<dim3(3, 32, NB), 256, SMEM_BYTES>>>(5, nullptr, nullptr);   // fused projections
    k_sample<<<(NB * LP * 64 + 255) / 256, 256>>>(bbox);
    k_gemm<<<dim3(2, 32, NB), 256, SMEM_BYTES>>>(6, outb, nullptr);      // out projection
    k_gemm<<<dim3(4, 32, NB), 256, SMEM_BYTES>>>(7, nullptr, (float*)d_out); // cv2
}

// round 5
// speedup vs baseline: 3.4074x; 1.0041x over previous
#include <cuda_runtime.h>
#include <cuda_bf16.h>
#include <cstdint>

#define NB 8
#define LP 4096

// ======================= PTX helpers (baseline ISA only) =======================
__device__ __forceinline__ uint32_t smem_u32(const void* p){
    uint32_t a;
    asm("{ .reg .u64 t; cvta.to.shared.u64 t, %1; cvt.u32.u64 %0, t; }" : "=r"(a) : "l"(p));
    return a;
}
__device__ __forceinline__ void cpa16(uint32_t dst, const void* src, uint32_t nbytes){
    asm volatile("cp.async.cg.shared.global [%0], [%1], 16, %2;"
        :: "r"(dst), "l"(src), "r"(nbytes) : "memory");
}
#define CP_COMMIT() asm volatile("cp.async.commit_group;" ::: "memory")
#define CP_WAIT1()  asm volatile("cp.async.wait_group 1;" ::: "memory")

__device__ __forceinline__ void ldsm4(uint32_t* r, uint32_t a){
    asm volatile("ldmatrix.sync.aligned.m8n8.x4.shared.b16 {%0,%1,%2,%3}, [%4];"
        : "=r"(r[0]), "=r"(r[1]), "=r"(r[2]), "=r"(r[3]) : "r"(a));
}
__device__ __forceinline__ void mma16816(float* c, const uint32_t* a, uint32_t b0, uint32_t b1){
    asm volatile("mma.sync.aligned.m16n8k16.row.col.f32.bf16.bf16.f32 "
        "{%0,%1,%2,%3}, {%4,%5,%6,%7}, {%8,%9}, {%0,%1,%2,%3};"
        : "+f"(c[0]), "+f"(c[1]), "+f"(c[2]), "+f"(c[3])
        : "r"(a[0]), "r"(a[1]), "r"(a[2]), "r"(a[3]), "r"(b0), "r"(b1));
}
#define SW128(o) ((o) ^ (((o) >> 3) & 0x70))

// ======================= device scratch =======================
__device__ __nv_bfloat16 g_xah[(size_t)NB*LP*512], g_xal[(size_t)NB*LP*512];
__device__ __nv_bfloat16 g_y0h[(size_t)NB*LP*512], g_y0l[(size_t)NB*LP*512];
__device__ __nv_bfloat16 g_t0h[(size_t)NB*LP*256], g_t0l[(size_t)NB*LP*256];
__device__ __nv_bfloat16 g_b1h[(size_t)NB*LP*256], g_b1l[(size_t)NB*LP*256];
__device__ __nv_bfloat16 g_t1h[(size_t)NB*LP*256], g_t1l[(size_t)NB*LP*256];
__device__ __nv_bfloat16 g_b2h[(size_t)NB*LP*256], g_b2l[(size_t)NB*LP*256];
__device__ float g_value[(size_t)NB*LP*256];
__device__ float g_off [(size_t)NB*LP*64];
__device__ float g_awL [(size_t)NB*LP*32];
__device__ __nv_bfloat16 g_smh[(size_t)NB*LP*256], g_sml[(size_t)NB*LP*256];
__device__ __nv_bfloat16 g_ath[(size_t)NB*LP*256], g_atl[(size_t)NB*LP*256];

__device__ __nv_bfloat16 g_wcv1h[512*512],  g_wcv1l[512*512];
__device__ __nv_bfloat16 g_wc0h[256*2304],  g_wc0l[256*2304];
__device__ __nv_bfloat16 g_wc1h[256*2304],  g_wc1l[256*2304];
__device__ __nv_bfloat16 g_wc2h[256*2304],  g_wc2l[256*2304];
__device__ __nv_bfloat16 g_wc3h[256*2304],  g_wc3l[256*2304];
__device__ __nv_bfloat16 g_wcth[384*256],   g_wctl[384*256];
__device__ float         g_bct[384];
__device__ __nv_bfloat16 g_woh[256*256],    g_wol[256*256];
__device__ __nv_bfloat16 g_wv2h[512*1280],  g_wv2l[512*1280];

__device__ __forceinline__ void split2(float v, __nv_bfloat16& h, __nv_bfloat16& l){
    h = __float2bfloat16(v);
    l = __float2bfloat16(v - __bfloat162float(h));
}
__device__ __forceinline__ float silu_f(float v){ return v / (1.f + __expf(-v)); }

// ======================= conversion kernels =======================
__global__ void k_cvt_x(const float* __restrict__ x){
    __shared__ float t[32][33];
    int b = blockIdx.z, l0 = blockIdx.x<<5, c0 = blockIdx.y<<5;
    int tx = threadIdx.x, ty = threadIdx.y;
#pragma unroll
    for (int i=0;i<32;i+=8)
        t[ty+i][tx] = x[((size_t)((b<<9)+(c0+ty+i))<<12) + l0 + tx];
    __syncthreads();
#pragma unroll
    for (int i=0;i<32;i+=8){
        float v = t[tx][ty+i];
        size_t o = ((size_t)((b<<12)+(l0+ty+i))<<9) + c0 + tx;
        __nv_bfloat16 h, l2; split2(v, h, l2);
        g_xah[o] = h; g_xal[o] = l2;
    }
}

// all weight conversions in one launch; branch on blockIdx.y
__global__ void k_cvt_w(const float* __restrict__ cv1w, const float* __restrict__ cv2w,
                        const float* __restrict__ c0, const float* __restrict__ c1,
                        const float* __restrict__ c2, const float* __restrict__ c3,
                        const float* __restrict__ vw, const float* __restrict__ vb2,
                        const float* __restrict__ ow2, const float* __restrict__ ob2,
                        const float* __restrict__ aw2, const float* __restrict__ ab2,
                        const float* __restrict__ outw){
    int which = blockIdx.y;
    size_t i = (size_t)blockIdx.x*256 + threadIdx.x;
    if (which == 0){
        if (i >= (size_t)512*512) return;
        __nv_bfloat16 h, l2; split2(cv1w[i], h, l2);
        g_wcv1h[i] = h; g_wcv1l[i] = l2;
    } else if (which == 1){
        if (i >= (size_t)512*1280) return;
        __nv_bfloat16 h, l2; split2(cv2w[i], h, l2);
        g_wv2h[i] = h; g_wv2l[i] = l2;
    } else if (which <= 5){
        if (i >= (size_t)256*2304) return;
        const float* src = (which==2)?c0:(which==3)?c1:(which==4)?c2:c3;
        __nv_bfloat16 *dh = (which==2)?g_wc0h:(which==3)?g_wc1h:(which==4)?g_wc2h:g_wc3h;
        __nv_bfloat16 *dl = (which==2)?g_wc0l:(which==3)?g_wc1l:(which==4)?g_wc2l:g_wc3l;
        int o = (int)(i / 2304);
        int k = (int)(i - (size_t)o*2304);
        int j = k >> 8, ic = k & 255;
        __nv_bfloat16 h, l2; split2(src[((size_t)o*256 + ic)*9 + j], h, l2);
        dh[i] = h; dl[i] = l2;
    } else if (which == 6){
        if (i >= (size_t)384*256) return;
        int n = (int)(i >> 8), c = (int)(i & 255);
        float v = 0.f;
        if (n < 256)       v = vw[(size_t)c*256 + n];
        else if (n < 320)  v = ow2[(size_t)c*64 + (n-256)];
        else if (n < 352)  v = aw2[(size_t)c*32 + (n-320)];
        __nv_bfloat16 h, l2; split2(v, h, l2);
        g_wcth[i] = h; g_wctl[i] = l2;
        if (c == 0){
            float bv = 0.f;
            if (n < 256) bv = vb2[n];
            else if (n < 320) bv = ob2[n-256];
            else if (n < 352) bv = ab2[n-320];
            g_bct[n] = bv;
        }
    } else {
        if (i >= (size_t)256*256) return;
        int n = (int)(i >> 8), c = (int)(i & 255);
        __nv_bfloat16 h, l2; split2(outw[(size_t)c*256 + n], h, l2);
        g_woh[i] = h; g_wol[i] = l2;
    }
}

// ======================= main GEMM (mma.sync bf16, 3-term fp32 emulation) =======================
// CTA tile 128(m) x 128(n) x 32(k). 8 warps (2x4), warp tile 64x32.
// SMEM buffer (32KB): A 16KB: row m(0..127) x [Ah 64B | Al 64B] SW128-swizzled;
//                     B 16KB: row n(0..127) x [Bh 64B | Bl 64B]. 3-deep ring. 2 CTAs/SM.
#define SMEM_BYTES (3*32768)

__global__ __launch_bounds__(256, 2) void k_gemm(int stage, const float* __restrict__ ebias,
                                                 float* __restrict__ dout)
{
    extern __shared__ char smc[];
    const uint32_t sb = smem_u32(smc);
    const int tid = threadIdx.x;
    const int wid = tid >> 5, lid = tid & 31;
    const int b  = blockIdx.z;
    const int l0 = blockIdx.y << 7;
    const int n0 = blockIdx.x << 7;

    int K;
    const __nv_bfloat16 *wh, *wl;
    switch (stage){
        case 0: K = 512;  wh = g_wcv1h; wl = g_wcv1l; break;
        case 1: K = 2304; wh = g_wc0h;  wl = g_wc0l;  break;
        case 2: K = 2304; wh = g_wc1h;  wl = g_wc1l;  break;
        case 3: K = 2304; wh = g_wc2h;  wl = g_wc2l;  break;
        case 4: K = 2304; wh = g_wc3h;  wl = g_wc3l;  break;
        case 5: K = 256;  wh = g_wcth;  wl = g_wctl;  break;
        case 6: K = 256;  wh = g_woh;   wl = g_wol;   break;
        default:K = 1280; wh = g_wv2h;  wl = g_wv2l;  break;
    }
    const int NC = K >> 5;          // k32 chunks

    float acc[4][4][4];
#pragma unroll
    for (int i=0;i<4;i++)
#pragma unroll
    for (int j=0;j<4;j++)
#pragma unroll
    for (int e=0;e<4;e++) acc[i][j][e] = 0.f;

    const int wm = wid >> 2, wn = wid & 3;

    auto issue = [&](int cc){
        const __nv_bfloat16 *ah, *al; int ach, acb, ady = 0, adx = 0; bool acv = false;
        const int k0c = cc << 5;
        if (stage == 0){ ah = g_xah; al = g_xal; ach = 512; acb = k0c; }
        else if (stage <= 4){
            int j = cc >> 3; int jd = j / 3;
            ady = jd - 1; adx = j - jd*3 - 1; acv = true;
            int ic0 = (cc & 7) << 5;
            if (stage == 1){ ah = g_y0h; al = g_y0l; ach = 512; acb = 256 + ic0; }
            else if (stage == 2){ ah = g_t0h; al = g_t0l; ach = 256; acb = ic0; }
            else if (stage == 3){ ah = g_b1h; al = g_b1l; ach = 256; acb = ic0; }
            else { ah = g_t1h; al = g_t1l; ach = 256; acb = ic0; }
        }
        else if (stage == 5){ ah = g_b2h; al = g_b2l; ach = 256; acb = k0c; }
        else if (stage == 6){ ah = g_smh; al = g_sml; ach = 256; acb = k0c; }
        else {
            if (k0c < 512)      { ah = g_y0h; al = g_y0l; ach = 512; acb = k0c; }
            else if (k0c < 768) { ah = g_b1h; al = g_b1l; ach = 256; acb = k0c - 512; }
            else if (k0c < 1024){ ah = g_b2h; al = g_b2l; ach = 256; acb = k0c - 768; }
            else                { ah = g_ath; al = g_atl; ach = 256; acb = k0c - 1024; }
        }
        uint32_t base = sb + (uint32_t)(cc % 3) * 32768u;
#pragma unroll
        for (int it2 = 0; it2 < 2; it2++){
            int it = tid + (it2 << 8);     // 0..511
            int m = it >> 2, u = it & 3;   // row, 16B unit within 64B half
            uint32_t oh = ((uint32_t)m << 7) + ((uint32_t)u << 4);      // hi half
            uint32_t ol = oh + 64;                                      // lo half
            uint32_t swh = SW128(oh), swl = SW128(ol);
            size_t off = 0; uint32_t nb = 16;
            if (acv){
                int p = l0 + m;
                int sy = (p >> 6) + ady, sx = (p & 63) + adx;
                if ((unsigned)sy < 64u && (unsigned)sx < 64u)
                    off = (size_t)((b<<12) + (sy<<6) + sx) * ach + acb + (u<<3);
                else nb = 0;
            } else {
                off = (size_t)((b<<12) + l0 + m) * ach + acb + (u<<3);
            }
            cpa16(base + swh,          ah + off, nb);
            cpa16(base + swl,          al + off, nb);
            size_t woff = (size_t)(n0 + m) * K + k0c + (u<<3);
            cpa16(base + 16384 + swh,  wh + woff, 16);
            cpa16(base + 16384 + swl,  wl + woff, 16);
        }
        CP_COMMIT();
    };

    issue(0);
    issue(1);
    for (int cc = 0; cc < NC; cc++){
        CP_WAIT1();
        __syncthreads();
        if (cc + 2 < NC) issue(cc + 2);
        uint32_t ua = sb + (uint32_t)(cc % 3) * 32768u;
        uint32_t ub = ua + 16384u;
        const int mat = lid >> 3, r8 = lid & 7;
#pragma unroll
        for (int ks = 0; ks < 2; ks++){
            uint32_t bh[2][4], blf[2][4], af[4][4];
#pragma unroll
            for (int bi = 0; bi < 2; bi++){
                int row = (wn << 5) + (bi << 4) + ((mat >> 1) << 3) + r8;
                uint32_t o = ((uint32_t)row << 7) + (ks << 5) + ((mat & 1) << 4);
                ldsm4(bh[bi],  ub + SW128(o));
                uint32_t o2 = o + 64;
                ldsm4(blf[bi], ub + SW128(o2));
            }
#pragma unroll
            for (int mi = 0; mi < 4; mi++){
                int row = (wm << 6) + (mi << 4) + ((mat & 1) << 3) + r8;
                uint32_t o = ((uint32_t)row << 7) + (ks << 5) + ((mat >> 1) << 4);
                ldsm4(af[mi], ua + SW128(o));
            }
#pragma unroll
            for (int mi = 0; mi < 4; mi++)
#pragma unroll
            for (int ni = 0; ni < 4; ni++){
                uint32_t b0h = bh[ni >> 1][(ni & 1) << 1],  b1h = bh[ni >> 1][((ni & 1) << 1) + 1];
                uint32_t b0l = blf[ni >> 1][(ni & 1) << 1], b1l = blf[ni >> 1][((ni & 1) << 1) + 1];
                mma16816(acc[mi][ni], af[mi], b0h, b1h);
                mma16816(acc[mi][ni], af[mi], b0l, b1l);
            }
#pragma unroll
            for (int mi = 0; mi < 4; mi++){
                int row = (wm << 6) + (mi << 4) + ((mat & 1) << 3) + r8;
                uint32_t o = ((uint32_t)row << 7) + (ks << 5) + ((mat >> 1) << 4) + 64;
                ldsm4(af[mi], ua + SW128(o));
            }
#pragma unroll
            for (int mi = 0; mi < 4; mi++)
#pragma unroll
            for (int ni = 0; ni < 4; ni++){
                uint32_t b0h = bh[ni >> 1][(ni & 1) << 1], b1h = bh[ni >> 1][((ni & 1) << 1) + 1];
                mma16816(acc[mi][ni], af[mi], b0h, b1h);
            }
        }
    }

    // ---------------- epilogue ----------------
    const int qr = lid >> 2;
    const int qc = (lid & 3) << 1;
#pragma unroll
    for (int mi = 0; mi < 4; mi++){
#pragma unroll
        for (int ni = 0; ni < 4; ni++){
            float* c = acc[mi][ni];
            int ch = (wn << 5) + (ni << 3) + qc;
            int r0 = (wm << 6) + (mi << 4) + qr;
            int r1 = r0 + 8;

            if (stage <= 4){
                __nv_bfloat16 *dh, *dl2; int OC;
                if (stage == 0){ dh = g_y0h; dl2 = g_y0l; OC = 512; }
                else if (stage == 1){ dh = g_t0h; dl2 = g_t0l; OC = 256; }
                else if (stage == 2){ dh = g_b1h; dl2 = g_b1l; OC = 256; }
                else if (stage == 3){ dh = g_t1h; dl2 = g_t1l; OC = 256; }
                else { dh = g_b2h; dl2 = g_b2l; OC = 256; }
#pragma unroll
                for (int h2 = 0; h2 < 2; h2++){
                    int r = h2 ? r1 : r0;
                    float v0 = silu_f(c[2*h2]), v1 = silu_f(c[2*h2+1]);
                    __nv_bfloat16 h0, q0, h1, q1;
                    split2(v0, h0, q0); split2(v1, h1, q1);
                    size_t o = ((size_t)((b<<12) + l0 + r)) * OC + n0 + ch;
                    *(uint32_t*)&dh [o] = (uint32_t)__bfloat16_as_ushort(h0) | ((uint32_t)__bfloat16_as_ushort(h1) << 16);
                    *(uint32_t*)&dl2[o] = (uint32_t)__bfloat16_as_ushort(q0) | ((uint32_t)__bfloat16_as_ushort(q1) << 16);
                }
            } else if (stage == 5){
#pragma unroll
                for (int h2 = 0; h2 < 2; h2++){
                    int r = h2 ? r1 : r0;
                    size_t bl = (size_t)(b<<12) + l0 + r;
#pragma unroll
                    for (int e = 0; e < 2; e++){
                        int ng = n0 + ch + e;
                        float v = c[2*h2 + e] + g_bct[ng];
                        if (ng < 256)      g_value[bl*256 + ng] = v;
                        else if (ng < 320) g_off [bl*64 + (ng - 256)] = v;
                        else if (ng < 352) g_awL [bl*32 + (ng - 320)] = v;
                    }
                }
            } else if (stage == 6){
#pragma unroll
                for (int h2 = 0; h2 < 2; h2++){
                    int r = h2 ? r1 : r0;
                    float v0 = c[2*h2]     + ebias[n0 + ch];
                    float v1 = c[2*h2 + 1] + ebias[n0 + ch + 1];
                    __nv_bfloat16 h0, q0, h1, q1;
                    split2(v0, h0, q0); split2(v1, h1, q1);
                    size_t o = ((size_t)((b<<12) + l0 + r)) * 256 + n0 + ch;
                    *(uint32_t*)&g_ath[o] = (uint32_t)__bfloat16_as_ushort(h0) | ((uint32_t)__bfloat16_as_ushort(h1) << 16);
                    *(uint32_t*)&g_atl[o] = (uint32_t)__bfloat16_as_ushort(q0) | ((uint32_t)__bfloat16_as_ushort(q1) << 16);
                }
            } else {
#pragma unroll
                for (int h2 = 0; h2 < 2; h2++){
                    int r = h2 ? r1 : r0;
#pragma unroll
                    for (int e = 0; e < 2; e++){
                        float v = silu_f(c[2*h2 + e]);
                        dout[((size_t)((b << 9) + n0 + ch + e) << 12) + l0 + r] = v;
                    }
                }
            }
        }
    }
}

// ======================= deformable sampling =======================
__global__ void k_sample(const float* __restrict__ bbox){
    int g = blockIdx.x * blockDim.x + threadIdx.x;
    if (g >= NB * LP * 64) return;
    int d4 = g & 7;
    int hd = (g >> 3) & 7;
    int l  = (g >> 6) & 4095;
    int b  = g >> 18;
    size_t bl = (size_t)b * LP + l;
    float bx = bbox[bl*2 + 0];
    float by = bbox[bl*2 + 1];
    const float* op = g_off + bl*64 + hd*8;
    const float* ap = g_awL + bl*32 + hd*4;

    float a0 = ap[0], a1 = ap[1], a2 = ap[2], a3 = ap[3];
    float mx = fmaxf(fmaxf(a0, a1), fmaxf(a2, a3));
    float e0 = __expf(a0 - mx), e1 = __expf(a1 - mx), e2 = __expf(a2 - mx), e3 = __expf(a3 - mx);
    float inv = 1.f / (e0 + e1 + e2 + e3);
    float wp[4] = {e0*inv, e1*inv, e2*inv, e3*inv};

    const float* vb = g_value + ((size_t)b * LP) * 256 + hd*32 + (d4 << 2);
    float4 acc = make_float4(0.f, 0.f, 0.f, 0.f);
#pragma unroll
    for (int p = 0; p < 4; p++){
        float lx = bx + op[p*2 + 0] * 0.015625f;
        float ly = by + op[p*2 + 1] * 0.015625f;
        float gx = lx * 64.f - 0.5f;
        float gy = ly * 64.f - 0.5f;
        float fx = floorf(gx), fy = floorf(gy);
        float wx1 = gx - fx, wy1 = gy - fy;
        float wx0 = 1.f - wx1, wy0 = 1.f - wy1;
        int ix = (int)fx, iy = (int)fy;
        float awp = wp[p];
#pragma unroll
        for (int c2 = 0; c2 < 4; c2++){
            int cx = ix + (c2 & 1);
            int cy = iy + (c2 >> 1);
            if ((unsigned)cx < 64u && (unsigned)cy < 64u){
                float wgt = awp * ((c2 & 1) ? wx1 : wx0) * ((c2 >> 1) ? wy1 : wy0);
                float4 v = *(const float4*)&vb[(size_t)((cy << 6) + cx) * 256];
                acc.x += wgt * v.x; acc.y += wgt * v.y;
                acc.z += wgt * v.z; acc.w += wgt * v.w;
            }
        }
    }
    size_t o = bl*256 + hd*32 + (d4 << 2);
    __nv_bfloat16 h, l2;
    split2(acc.x, h, l2); g_smh[o+0] = h; g_sml[o+0] = l2;
    split2(acc.y, h, l2); g_smh[o+1] = h; g_sml[o+1] = l2;
    split2(acc.z, h, l2); g_smh[o+2] = h; g_sml[o+2] = l2;
    split2(acc.w, h, l2); g_smh[o+3] = h; g_sml[o+3] = l2;
}

// ======================= launch =======================
extern "C" void kernel_launch(void* const* d_in, const int* in_sizes, int n_in,
                              void* d_out, int out_size) {
    const float* x    = (const float*)d_in[0];
    const float* bbox = (const float*)d_in[1];
    const float* cv1w = (const float*)d_in[3];
    const float* m0c1 = (const float*)d_in[4];
    const float* m0c2 = (const float*)d_in[5];
    const float* m1c1 = (const float*)d_in[6];
    const float* m1c2 = (const float*)d_in[7];
    const float* vw   = (const float*)d_in[8];
    const float* vb   = (const float*)d_in[9];
    const float* ow   = (const float*)d_in[10];
    const float* ob   = (const float*)d_in[11];
    const float* aww  = (const float*)d_in[12];
    const float* awb  = (const float*)d_in[13];
    const float* outw = (const float*)d_in[14];
    const float* outb = (const float*)d_in[15];
    const float* cv2w = (const float*)d_in[16];

    cudaFuncSetAttribute(k_gemm, cudaFuncAttributeMaxDynamicSharedMemorySize, SMEM_BYTES);

    k_cvt_x<<<dim3(128, 16, NB), dim3(32, 8)>>>(x);
    k_cvt_w<<<dim3(2560, 8), 256>>>(cv1w, cv2w, m0c1, m0c2, m1c1, m1c2,
                                    vw, vb, ow, ob, aww, awb, outw);

    k_gemm<<<dim3(4, 32, NB), 256, SMEM_BYTES>>>(0, nullptr, nullptr);   // cv1
    k_gemm<<<dim3(2, 32, NB), 256, SMEM_BYTES>>>(1, nullptr, nullptr);   // m0_cv1
    k_gemm<<<dim3(2, 32, NB), 256, SMEM_BYTES>>>(2, nullptr, nullptr);   // m0_cv2
    k_gemm<<<dim3(2, 32, NB), 256, SMEM_BYTES>>>(3, nullptr, nullptr);   // m1_cv1
    k_gemm<<<dim3(2, 32, NB), 256, SMEM_BYTES>>>(4, nullptr, nullptr);   // m1_cv2
    k_gemm<<<dim3(3, 32, NB), 256, SMEM_BYTES>>>(5, nullptr, nullptr);   // fused projections
    k_sample<<<(NB * LP * 64 + 255) / 256, 256>>>(bbox);
    k_gemm<<<dim3(2, 32, NB), 256, SMEM_BYTES>>>(6, outb, nullptr);      // out projection
    k_gemm<<<dim3(4, 32, NB), 256, SMEM_BYTES>>>(7, nullptr, (float*)d_out); // cv2
}

// round 7
// speedup vs baseline: 3.4102x; 1.0008x over previous
#include <cuda_runtime.h>
#include <cuda_bf16.h>
#include <cstdint>

#define NB 8
#define LP 4096

// ======================= PTX helpers (baseline ISA only) =======================
__device__ __forceinline__ uint32_t smem_u32(const void* p){
    uint32_t a;
    asm("{ .reg .u64 t; cvta.to.shared.u64 t, %1; cvt.u32.u64 %0, t; }" : "=r"(a) : "l"(p));
    return a;
}
__device__ __forceinline__ void cpa16(uint32_t dst, const void* src, uint32_t nbytes){
    asm volatile("cp.async.cg.shared.global [%0], [%1], 16, %2;"
        :: "r"(dst), "l"(src), "r"(nbytes) : "memory");
}
#define CP_COMMIT() asm volatile("cp.async.commit_group;" ::: "memory")
#define CP_WAIT1()  asm volatile("cp.async.wait_group 1;" ::: "memory")

__device__ __forceinline__ void ldsm4(uint32_t* r, uint32_t a){
    asm volatile("ldmatrix.sync.aligned.m8n8.x4.shared.b16 {%0,%1,%2,%3}, [%4];"
        : "=r"(r[0]), "=r"(r[1]), "=r"(r[2]), "=r"(r[3]) : "r"(a));
}
__device__ __forceinline__ void mma16816(float* c, const uint32_t* a, uint32_t b0, uint32_t b1){
    asm volatile("mma.sync.aligned.m16n8k16.row.col.f32.bf16.bf16.f32 "
        "{%0,%1,%2,%3}, {%4,%5,%6,%7}, {%8,%9}, {%0,%1,%2,%3};"
        : "+f"(c[0]), "+f"(c[1]), "+f"(c[2]), "+f"(c[3])
        : "r"(a[0]), "r"(a[1]), "r"(a[2]), "r"(a[3]), "r"(b0), "r"(b1));
}
#define SW128(o) ((o) ^ (((o) >> 3) & 0x70))

// ======================= device scratch =======================
__device__ __nv_bfloat16 g_xah[(size_t)NB*LP*512], g_xal[(size_t)NB*LP*512];
__device__ __nv_bfloat16 g_y0h[(size_t)NB*LP*512], g_y0l[(size_t)NB*LP*512];
__device__ __nv_bfloat16 g_t0h[(size_t)NB*LP*256], g_t0l[(size_t)NB*LP*256];
__device__ __nv_bfloat16 g_b1h[(size_t)NB*LP*256], g_b1l[(size_t)NB*LP*256];
__device__ __nv_bfloat16 g_t1h[(size_t)NB*LP*256], g_t1l[(size_t)NB*LP*256];
__device__ __nv_bfloat16 g_b2h[(size_t)NB*LP*256], g_b2l[(size_t)NB*LP*256];
__device__ float g_value[(size_t)NB*LP*256];
__device__ float g_off [(size_t)NB*LP*64];
__device__ float g_awL [(size_t)NB*LP*32];
__device__ __nv_bfloat16 g_smh[(size_t)NB*LP*256], g_sml[(size_t)NB*LP*256];
__device__ __nv_bfloat16 g_ath[(size_t)NB*LP*256], g_atl[(size_t)NB*LP*256];

__device__ __nv_bfloat16 g_wcv1h[512*512],  g_wcv1l[512*512];
__device__ __nv_bfloat16 g_wc0h[256*2304],  g_wc0l[256*2304];
__device__ __nv_bfloat16 g_wc1h[256*2304],  g_wc1l[256*2304];
__device__ __nv_bfloat16 g_wc2h[256*2304],  g_wc2l[256*2304];
__device__ __nv_bfloat16 g_wc3h[256*2304],  g_wc3l[256*2304];
__device__ __nv_bfloat16 g_wcth[384*256],   g_wctl[384*256];
__device__ float         g_bct[384];
__device__ __nv_bfloat16 g_woh[256*256],    g_wol[256*256];
__device__ __nv_bfloat16 g_wv2h[512*1280],  g_wv2l[512*1280];

__device__ __forceinline__ void split2(float v, __nv_bfloat16& h, __nv_bfloat16& l){
    h = __float2bfloat16(v);
    l = __float2bfloat16(v - __bfloat162float(h));
}
__device__ __forceinline__ float silu_f(float v){ return v / (1.f + __expf(-v)); }

// ======================= conversion kernels =======================
__global__ void k_cvt_x(const float* __restrict__ x){
    __shared__ float t[32][33];
    int b = blockIdx.z, l0 = blockIdx.x<<5, c0 = blockIdx.y<<5;
    int tx = threadIdx.x, ty = threadIdx.y;
#pragma unroll
    for (int i=0;i<32;i+=8)
        t[ty+i][tx] = x[((size_t)((b<<9)+(c0+ty+i))<<12) + l0 + tx];
    __syncthreads();
#pragma unroll
    for (int i=0;i<32;i+=8){
        float v = t[tx][ty+i];
        size_t o = ((size_t)((b<<12)+(l0+ty+i))<<9) + c0 + tx;
        __nv_bfloat16 h, l2; split2(v, h, l2);
        g_xah[o] = h; g_xal[o] = l2;
    }
}

// all weight conversions in one launch; branch on blockIdx.y
__global__ void k_cvt_w(const float* __restrict__ cv1w, const float* __restrict__ cv2w,
                        const float* __restrict__ c0, const float* __restrict__ c1,
                        const float* __restrict__ c2, const float* __restrict__ c3,
                        const float* __restrict__ vw, const float* __restrict__ vb2,
                        const float* __restrict__ ow2, const float* __restrict__ ob2,
                        const float* __restrict__ aw2, const float* __restrict__ ab2,
                        const float* __restrict__ outw){
    int which = blockIdx.y;
    size_t i = (size_t)blockIdx.x*256 + threadIdx.x;
    if (which == 0){
        if (i >= (size_t)512*512) return;
        __nv_bfloat16 h, l2; split2(cv1w[i], h, l2);
        g_wcv1h[i] = h; g_wcv1l[i] = l2;
    } else if (which == 1){
        if (i >= (size_t)512*1280) return;
        __nv_bfloat16 h, l2; split2(cv2w[i], h, l2);
        g_wv2h[i] = h; g_wv2l[i] = l2;
    } else if (which <= 5){
        if (i >= (size_t)256*2304) return;
        const float* src = (which==2)?c0:(which==3)?c1:(which==4)?c2:c3;
        __nv_bfloat16 *dh = (which==2)?g_wc0h:(which==3)?g_wc1h:(which==4)?g_wc2h:g_wc3h;
        __nv_bfloat16 *dl = (which==2)?g_wc0l:(which==3)?g_wc1l:(which==4)?g_wc2l:g_wc3l;
        int o = (int)(i / 2304);
        int k = (int)(i - (size_t)o*2304);
        int j = k >> 8, ic = k & 255;
        __nv_bfloat16 h, l2; split2(src[((size_t)o*256 + ic)*9 + j], h, l2);
        dh[i] = h; dl[i] = l2;
    } else if (which == 6){
        if (i >= (size_t)384*256) return;
        int n = (int)(i >> 8), c = (int)(i & 255);
        float v = 0.f;
        if (n < 256)       v = vw[(size_t)c*256 + n];
        else if (n < 320)  v = ow2[(size_t)c*64 + (n-256)];
        else if (n < 352)  v = aw2[(size_t)c*32 + (n-320)];
        __nv_bfloat16 h, l2; split2(v, h, l2);
        g_wcth[i] = h; g_wctl[i] = l2;
        if (c == 0){
            float bv = 0.f;
            if (n < 256) bv = vb2[n];
            else if (n < 320) bv = ob2[n-256];
            else if (n < 352) bv = ab2[n-320];
            g_bct[n] = bv;
        }
    } else {
        if (i >= (size_t)256*256) return;
        int n = (int)(i >> 8), c = (int)(i & 255);
        __nv_bfloat16 h, l2; split2(outw[(size_t)c*256 + n], h, l2);
        g_woh[i] = h; g_wol[i] = l2;
    }
}

// ======================= main GEMM (mma.sync bf16, 3-term fp32 emulation) =======================
// CTA tile 128(m) x 128(n) x 32(k). 8 warps (2x4), warp tile 64x32.
// SMEM buffer (32KB): A 16KB: row m(0..127) x [Ah 64B | Al 64B] SW128-swizzled;
//                     B 16KB: row n(0..127) x [Bh 64B | Bl 64B]. 3-deep ring. 2 CTAs/SM.
#define SMEM_BYTES (3*32768)

__global__ __launch_bounds__(256, 2) void k_gemm(int stage, const float* __restrict__ ebias,
                                                 float* __restrict__ dout)
{
    extern __shared__ char smc[];
    const uint32_t sb = smem_u32(smc);
    const int tid = threadIdx.x;
    const int wid = tid >> 5, lid = tid & 31;
    const int b  = blockIdx.z;
    const int l0 = blockIdx.y << 7;
    const int n0 = blockIdx.x << 7;

    int K;
    const __nv_bfloat16 *wh, *wl;
    switch (stage){
        case 0: K = 512;  wh = g_wcv1h; wl = g_wcv1l; break;
        case 1: K = 2304; wh = g_wc0h;  wl = g_wc0l;  break;
        case 2: K = 2304; wh = g_wc1h;  wl = g_wc1l;  break;
        case 3: K = 2304; wh = g_wc2h;  wl = g_wc2l;  break;
        case 4: K = 2304; wh = g_wc3h;  wl = g_wc3l;  break;
        case 5: K = 256;  wh = g_wcth;  wl = g_wctl;  break;
        case 6: K = 256;  wh = g_woh;   wl = g_wol;   break;
        default:K = 1280; wh = g_wv2h;  wl = g_wv2l;  break;
    }
    const int NC = K >> 5;          // k32 chunks

    float acc[4][4][4];
#pragma unroll
    for (int i=0;i<4;i++)
#pragma unroll
    for (int j=0;j<4;j++)
#pragma unroll
    for (int e=0;e<4;e++) acc[i][j][e] = 0.f;

    const int wm = wid >> 2, wn = wid & 3;

    auto issue = [&](int cc){
        const __nv_bfloat16 *ah, *al; int ach, acb, ady = 0, adx = 0; bool acv = false;
        const int k0c = cc << 5;
        if (stage == 0){ ah = g_xah; al = g_xal; ach = 512; acb = k0c; }
        else if (stage <= 4){
            int j = cc >> 3; int jd = j / 3;
            ady = jd - 1; adx = j - jd*3 - 1; acv = true;
            int ic0 = (cc & 7) << 5;
            if (stage == 1){ ah = g_y0h; al = g_y0l; ach = 512; acb = 256 + ic0; }
            else if (stage == 2){ ah = g_t0h; al = g_t0l; ach = 256; acb = ic0; }
            else if (stage == 3){ ah = g_b1h; al = g_b1l; ach = 256; acb = ic0; }
            else { ah = g_t1h; al = g_t1l; ach = 256; acb = ic0; }
        }
        else if (stage == 5){ ah = g_b2h; al = g_b2l; ach = 256; acb = k0c; }
        else if (stage == 6){ ah = g_smh; al = g_sml; ach = 256; acb = k0c; }
        else {
            if (k0c < 512)      { ah = g_y0h; al = g_y0l; ach = 512; acb = k0c; }
            else if (k0c < 768) { ah = g_b1h; al = g_b1l; ach = 256; acb = k0c - 512; }
            else if (k0c < 1024){ ah = g_b2h; al = g_b2l; ach = 256; acb = k0c - 768; }
            else                { ah = g_ath; al = g_atl; ach = 256; acb = k0c - 1024; }
        }
        uint32_t base = sb + (uint32_t)(cc % 3) * 32768u;
#pragma unroll
        for (int it2 = 0; it2 < 2; it2++){
            int it = tid + (it2 << 8);     // 0..511
            int m = it >> 2, u = it & 3;   // row, 16B unit within 64B half
            uint32_t oh = ((uint32_t)m << 7) + ((uint32_t)u << 4);      // hi half
            uint32_t ol = oh + 64;                                      // lo half
            uint32_t swh = SW128(oh), swl = SW128(ol);
            size_t off = 0; uint32_t nb = 16;
            if (acv){
                int p = l0 + m;
                int sy = (p >> 6) + ady, sx = (p & 63) + adx;
                if ((unsigned)sy < 64u && (unsigned)sx < 64u)
                    off = (size_t)((b<<12) + (sy<<6) + sx) * ach + acb + (u<<3);
                else nb = 0;
            } else {
                off = (size_t)((b<<12) + l0 + m) * ach + acb + (u<<3);
            }
            cpa16(base + swh,          ah + off, nb);
            cpa16(base + swl,          al + off, nb);
            size_t woff = (size_t)(n0 + m) * K + k0c + (u<<3);
            cpa16(base + 16384 + swh,  wh + woff, 16);
            cpa16(base + 16384 + swl,  wl + woff, 16);
        }
        CP_COMMIT();
    };

    issue(0);
    issue(1);
    for (int cc = 0; cc < NC; cc++){
        CP_WAIT1();
        __syncthreads();
        if (cc + 2 < NC) issue(cc + 2);
        uint32_t ua = sb + (uint32_t)(cc % 3) * 32768u;
        uint32_t ub = ua + 16384u;
        const int mat = lid >> 3, r8 = lid & 7;
#pragma unroll
        for (int ks = 0; ks < 2; ks++){
            uint32_t bh[2][4], blf[2][4], af[4][4];
            // hoisted fragment addresses for this ks
            uint32_t aaddr[4], baddr[2];
#pragma unroll
            for (int mi = 0; mi < 4; mi++){
                int row = (wm << 6) + (mi << 4) + ((mat & 1) << 3) + r8;
                uint32_t o = ((uint32_t)row << 7) + (ks << 5) + ((mat >> 1) << 4);
                aaddr[mi] = ua + SW128(o);
            }
#pragma unroll
            for (int bi = 0; bi < 2; bi++){
                int row = (wn << 5) + (bi << 4) + ((mat >> 1) << 3) + r8;
                uint32_t o = ((uint32_t)row << 7) + (ks << 5) + ((mat & 1) << 4);
                baddr[bi] = ub + SW128(o);
            }
#pragma unroll
            for (int bi = 0; bi < 2; bi++){
                ldsm4(bh[bi],  baddr[bi]);
                uint32_t o2 = (baddr[bi] - ub) ;  // already swizzled; recompute lo
                (void)o2;
            }
            // recompute lo-half B addresses (swizzle of o+64)
#pragma unroll
            for (int bi = 0; bi < 2; bi++){
                int row = (wn << 5) + (bi << 4) + ((mat >> 1) << 3) + r8;
                uint32_t o = ((uint32_t)row << 7) + (ks << 5) + ((mat & 1) << 4) + 64;
                ldsm4(blf[bi], ub + SW128(o));
            }
#pragma unroll
            for (int mi = 0; mi < 4; mi++) ldsm4(af[mi], aaddr[mi]);

            // sweep 1: Ah * Bh  (16 independent MMAs)
#pragma unroll
            for (int mi = 0; mi < 4; mi++)
#pragma unroll
            for (int ni = 0; ni < 4; ni++)
                mma16816(acc[mi][ni], af[mi],
                         bh[ni >> 1][(ni & 1) << 1], bh[ni >> 1][((ni & 1) << 1) + 1]);

            // sweep 2: Ah * Bl  (same accs, 16 apart)
#pragma unroll
            for (int mi = 0; mi < 4; mi++)
#pragma unroll
            for (int ni = 0; ni < 4; ni++)
                mma16816(acc[mi][ni], af[mi],
                         blf[ni >> 1][(ni & 1) << 1], blf[ni >> 1][((ni & 1) << 1) + 1]);

            // reload A with lo halves
#pragma unroll
            for (int mi = 0; mi < 4; mi++){
                int row = (wm << 6) + (mi << 4) + ((mat & 1) << 3) + r8;
                uint32_t o = ((uint32_t)row << 7) + (ks << 5) + ((mat >> 1) << 4) + 64;
                ldsm4(af[mi], ua + SW128(o));
            }

            // sweep 3: Al * Bh
#pragma unroll
            for (int mi = 0; mi < 4; mi++)
#pragma unroll
            for (int ni = 0; ni < 4; ni++)
                mma16816(acc[mi][ni], af[mi],
                         bh[ni >> 1][(ni & 1) << 1], bh[ni >> 1][((ni & 1) << 1) + 1]);
        }
    }

    // ---------------- epilogue ----------------
    const int qr = lid >> 2;
    const int qc = (lid & 3) << 1;
#pragma unroll
    for (int mi = 0; mi < 4; mi++){
#pragma unroll
        for (int ni = 0; ni < 4; ni++){
            float* c = acc[mi][ni];
            int ch = (wn << 5) + (ni << 3) + qc;
            int r0 = (wm << 6) + (mi << 4) + qr;
            int r1 = r0 + 8;

            if (stage <= 4){
                __nv_bfloat16 *dh, *dl2; int OC;
                if (stage == 0){ dh = g_y0h; dl2 = g_y0l; OC = 512; }
                else if (stage == 1){ dh = g_t0h; dl2 = g_t0l; OC = 256; }
                else if (stage == 2){ dh = g_b1h; dl2 = g_b1l; OC = 256; }
                else if (stage == 3){ dh = g_t1h; dl2 = g_t1l; OC = 256; }
                else { dh = g_b2h; dl2 = g_b2l; OC = 256; }
#pragma unroll
                for (int h2 = 0; h2 < 2; h2++){
                    int r = h2 ? r1 : r0;
                    float v0 = silu_f(c[2*h2]), v1 = silu_f(c[2*h2+1]);
                    __nv_bfloat16 h0, q0, h1, q1;
                    split2(v0, h0, q0); split2(v1, h1, q1);
                    size_t o = ((size_t)((b<<12) + l0 + r)) * OC + n0 + ch;
                    *(uint32_t*)&dh [o] = (uint32_t)__bfloat16_as_ushort(h0) | ((uint32_t)__bfloat16_as_ushort(h1) << 16);
                    *(uint32_t*)&dl2[o] = (uint32_t)__bfloat16_as_ushort(q0) | ((uint32_t)__bfloat16_as_ushort(q1) << 16);
                }
            } else if (stage == 5){
#pragma unroll
                for (int h2 = 0; h2 < 2; h2++){
                    int r = h2 ? r1 : r0;
                    size_t bl = (size_t)(b<<12) + l0 + r;
#pragma unroll
                    for (int e = 0; e < 2; e++){
                        int ng = n0 + ch + e;
                        float v = c[2*h2 + e] + g_bct[ng];
                        if (ng < 256)      g_value[bl*256 + ng] = v;
                        else if (ng < 320) g_off [bl*64 + (ng - 256)] = v;
                        else if (ng < 352) g_awL [bl*32 + (ng - 320)] = v;
                    }
                }
            } else if (stage == 6){
#pragma unroll
                for (int h2 = 0; h2 < 2; h2++){
                    int r = h2 ? r1 : r0;
                    float v0 = c[2*h2]     + ebias[n0 + ch];
                    float v1 = c[2*h2 + 1] + ebias[n0 + ch + 1];
                    __nv_bfloat16 h0, q0, h1, q1;
                    split2(v0, h0, q0); split2(v1, h1, q1);
                    size_t o = ((size_t)((b<<12) + l0 + r)) * 256 + n0 + ch;
                    *(uint32_t*)&g_ath[o] = (uint32_t)__bfloat16_as_ushort(h0) | ((uint32_t)__bfloat16_as_ushort(h1) << 16);
                    *(uint32_t*)&g_atl[o] = (uint32_t)__bfloat16_as_ushort(q0) | ((uint32_t)__bfloat16_as_ushort(q1) << 16);
                }
            } else {
#pragma unroll
                for (int h2 = 0; h2 < 2; h2++){
                    int r = h2 ? r1 : r0;
#pragma unroll
                    for (int e = 0; e < 2; e++){
                        float v = silu_f(c[2*h2 + e]);
                        dout[((size_t)((b << 9) + n0 + ch + e) << 12) + l0 + r] = v;
                    }
                }
            }
        }
    }
}

// ======================= deformable sampling =======================
__global__ void k_sample(const float* __restrict__ bbox){
    int g = blockIdx.x * blockDim.x + threadIdx.x;
    if (g >= NB * LP * 64) return;
    int d4 = g & 7;
    int hd = (g >> 3) & 7;
    int l  = (g >> 6) & 4095;
    int b  = g >> 18;
    size_t bl = (size_t)b * LP + l;
    float bx = bbox[bl*2 + 0];
    float by = bbox[bl*2 + 1];
    const float* op = g_off + bl*64 + hd*8;
    const float* ap = g_awL + bl*32 + hd*4;

    float a0 = ap[0], a1 = ap[1], a2 = ap[2], a3 = ap[3];
    float mx = fmaxf(fmaxf(a0, a1), fmaxf(a2, a3));
    float e0 = __expf(a0 - mx), e1 = __expf(a1 - mx), e2 = __expf(a2 - mx), e3 = __expf(a3 - mx);
    float inv = 1.f / (e0 + e1 + e2 + e3);
    float wp[4] = {e0*inv, e1*inv, e2*inv, e3*inv};

    const float* vb = g_value + ((size_t)b * LP) * 256 + hd*32 + (d4 << 2);
    float4 acc = make_float4(0.f, 0.f, 0.f, 0.f);
#pragma unroll
    for (int p = 0; p < 4; p++){
        float lx = bx + op[p*2 + 0] * 0.015625f;
        float ly = by + op[p*2 + 1] * 0.015625f;
        float gx = lx * 64.f - 0.5f;
        float gy = ly * 64.f - 0.5f;
        float fx = floorf(gx), fy = floorf(gy);
        float wx1 = gx - fx, wy1 = gy - fy;
        float wx0 = 1.f - wx1, wy0 = 1.f - wy1;
        int ix = (int)fx, iy = (int)fy;
        float awp = wp[p];
#pragma unroll
        for (int c2 = 0; c2 < 4; c2++){
            int cx = ix + (c2 & 1);
            int cy = iy + (c2 >> 1);
            if ((unsigned)cx < 64u && (unsigned)cy < 64u){
                float wgt = awp * ((c2 & 1) ? wx1 : wx0) * ((c2 >> 1) ? wy1 : wy0);
                float4 v = *(const float4*)&vb[(size_t)((cy << 6) + cx) * 256];
                acc.x += wgt * v.x; acc.y += wgt * v.y;
                acc.z += wgt * v.z; acc.w += wgt * v.w;
            }
        }
    }
    size_t o = bl*256 + hd*32 + (d4 << 2);
    __nv_bfloat16 h, l2;
    split2(acc.x, h, l2); g_smh[o+0] = h; g_sml[o+0] = l2;
    split2(acc.y, h, l2); g_smh[o+1] = h; g_sml[o+1] = l2;
    split2(acc.z, h, l2); g_smh[o+2] = h; g_sml[o+2] = l2;
    split2(acc.w, h, l2); g_smh[o+3] = h; g_sml[o+3] = l2;
}

// ======================= launch =======================
extern "C" void kernel_launch(void* const* d_in, const int* in_sizes, int n_in,
                              void* d_out, int out_size) {
    const float* x    = (const float*)d_in[0];
    const float* bbox = (const float*)d_in[1];
    const float* cv1w = (const float*)d_in[3];
    const float* m0c1 = (const float*)d_in[4];
    const float* m0c2 = (const float*)d_in[5];
    const float* m1c1 = (const float*)d_in[6];
    const float* m1c2 = (const float*)d_in[7];
    const float* vw   = (const float*)d_in[8];
    const float* vb   = (const float*)d_in[9];
    const float* ow   = (const float*)d_in[10];
    const float* ob   = (const float*)d_in[11];
    const float* aww  = (const float*)d_in[12];
    const float* awb  = (const float*)d_in[13];
    const float* outw = (const float*)d_in[14];
    const float* outb = (const float*)d_in[15];
    const float* cv2w = (const float*)d_in[16];

    cudaFuncSetAttribute(k_gemm, cudaFuncAttributeMaxDynamicSharedMemorySize, SMEM_BYTES);

    k_cvt_x<<<dim3(128, 16, NB), dim3(32, 8)>>>(x);
    k_cvt_w<<<dim3(2560, 8), 256>>>(cv1w, cv2w, m0c1, m0c2, m1c1, m1c2,
                                    vw, vb, ow, ob, aww, awb, outw);

    k_gemm<<<dim3(4, 32, NB), 256, SMEM_BYTES>>>(0, nullptr, nullptr);   // cv1
    k_gemm<<<dim3(2, 32, NB), 256, SMEM_BYTES>>>(1, nullptr, nullptr);   // m0_cv1
    k_gemm<<<dim3(2, 32, NB), 256, SMEM_BYTES>>>(2, nullptr, nullptr);   // m0_cv2
    k_gemm<<<dim3(2, 32, NB), 256, SMEM_BYTES>>>(3, nullptr, nullptr);   // m1_cv1
    k_gemm<<<dim3(2, 32, NB), 256, SMEM_BYTES>>>(4, nullptr, nullptr);   // m1_cv2
    k_gemm<<<dim3(3, 32, NB), 256, SMEM_BYTES>>>(5, nullptr, nullptr);   // fused projections
    k_sample<<<(NB * LP * 64 + 255) / 256, 256>>>(bbox);
    k_gemm<<<dim3(2, 32, NB), 256, SMEM_BYTES>>>(6, outb, nullptr);      // out projection
    k_gemm<<<dim3(4, 32, NB), 256, SMEM_BYTES>>>(7, nullptr, (float*)d_out); // cv2
}

// round 8
// speedup vs baseline: 4.5730x; 1.3410x over previous
#include <cuda_runtime.h>
#include <cuda_fp16.h>
#include <cstdint>

#define NB 8
#define LP 4096

// ======================= PTX helpers (baseline ISA only) =======================
__device__ __forceinline__ uint32_t smem_u32(const void* p){
    uint32_t a;
    asm("{ .reg .u64 t; cvta.to.shared.u64 t, %1; cvt.u32.u64 %0, t; }" : "=r"(a) : "l"(p));
    return a;
}
__device__ __forceinline__ void cpa16(uint32_t dst, const void* src, uint32_t nbytes){
    asm volatile("cp.async.cg.shared.global [%0], [%1], 16, %2;"
        :: "r"(dst), "l"(src), "r"(nbytes) : "memory");
}
#define CP_COMMIT() asm volatile("cp.async.commit_group;" ::: "memory")
#define CP_WAIT1()  asm volatile("cp.async.wait_group 1;" ::: "memory")

__device__ __forceinline__ void ldsm4(uint32_t* r, uint32_t a){
    asm volatile("ldmatrix.sync.aligned.m8n8.x4.shared.b16 {%0,%1,%2,%3}, [%4];"
        : "=r"(r[0]), "=r"(r[1]), "=r"(r[2]), "=r"(r[3]) : "r"(a));
}
__device__ __forceinline__ void mma16816(float* c, const uint32_t* a, uint32_t b0, uint32_t b1){
    asm volatile("mma.sync.aligned.m16n8k16.row.col.f32.f16.f16.f32 "
        "{%0,%1,%2,%3}, {%4,%5,%6,%7}, {%8,%9}, {%0,%1,%2,%3};"
        : "+f"(c[0]), "+f"(c[1]), "+f"(c[2]), "+f"(c[3])
        : "r"(a[0]), "r"(a[1]), "r"(a[2]), "r"(a[3]), "r"(b0), "r"(b1));
}
#define SW128(o) ((o) ^ (((o) >> 3) & 0x70))

// ======================= device scratch =======================
// activations: single fp16
__device__ __half g_xa[(size_t)NB*LP*512];
__device__ __half g_y0[(size_t)NB*LP*512];
__device__ __half g_t0[(size_t)NB*LP*256];
__device__ __half g_b1[(size_t)NB*LP*256];
__device__ __half g_t1[(size_t)NB*LP*256];
__device__ __half g_b2[(size_t)NB*LP*256];
__device__ float g_value[(size_t)NB*LP*256];
__device__ float g_off [(size_t)NB*LP*64];
__device__ float g_awL [(size_t)NB*LP*32];
__device__ __half g_sm[(size_t)NB*LP*256];
__device__ __half g_at[(size_t)NB*LP*256];

// weights: 2-term fp16 (hi + lo)
__device__ __half g_wcv1h[512*512],  g_wcv1l[512*512];
__device__ __half g_wc0h[256*2304],  g_wc0l[256*2304];
__device__ __half g_wc1h[256*2304],  g_wc1l[256*2304];
__device__ __half g_wc2h[256*2304],  g_wc2l[256*2304];
__device__ __half g_wc3h[256*2304],  g_wc3l[256*2304];
__device__ __half g_wcth[384*256],   g_wctl[384*256];
__device__ float  g_bct[384];
__device__ __half g_woh[256*256],    g_wol[256*256];
__device__ __half g_wv2h[512*1280],  g_wv2l[512*1280];

__device__ __forceinline__ void split2h(float v, __half& h, __half& l){
    h = __float2half(v);
    l = __float2half(v - __half2float(h));
}
__device__ __forceinline__ float silu_f(float v){ return v / (1.f + __expf(-v)); }
__device__ __forceinline__ uint32_t packh2(float a, float b){
    __half2 hh = __floats2half2_rn(a, b);
    return *(uint32_t*)&hh;
}

// ======================= conversion kernels =======================
__global__ void k_cvt_x(const float* __restrict__ x){
    __shared__ float t[32][33];
    int b = blockIdx.z, l0 = blockIdx.x<<5, c0 = blockIdx.y<<5;
    int tx = threadIdx.x, ty = threadIdx.y;
#pragma unroll
    for (int i=0;i<32;i+=8)
        t[ty+i][tx] = x[((size_t)((b<<9)+(c0+ty+i))<<12) + l0 + tx];
    __syncthreads();
#pragma unroll
    for (int i=0;i<32;i+=8){
        size_t o = ((size_t)((b<<12)+(l0+ty+i))<<9) + c0 + tx;
        g_xa[o] = __float2half(t[tx][ty+i]);
    }
}

// all weight conversions in one launch; branch on blockIdx.y
__global__ void k_cvt_w(const float* __restrict__ cv1w, const float* __restrict__ cv2w,
                        const float* __restrict__ c0, const float* __restrict__ c1,
                        const float* __restrict__ c2, const float* __restrict__ c3,
                        const float* __restrict__ vw, const float* __restrict__ vb2,
                        const float* __restrict__ ow2, const float* __restrict__ ob2,
                        const float* __restrict__ aw2, const float* __restrict__ ab2,
                        const float* __restrict__ outw){
    int which = blockIdx.y;
    size_t i = (size_t)blockIdx.x*256 + threadIdx.x;
    if (which == 0){
        if (i >= (size_t)512*512) return;
        split2h(cv1w[i], g_wcv1h[i], g_wcv1l[i]);
    } else if (which == 1){
        if (i >= (size_t)512*1280) return;
        split2h(cv2w[i], g_wv2h[i], g_wv2l[i]);
    } else if (which <= 5){
        if (i >= (size_t)256*2304) return;
        const float* src = (which==2)?c0:(which==3)?c1:(which==4)?c2:c3;
        __half *dh = (which==2)?g_wc0h:(which==3)?g_wc1h:(which==4)?g_wc2h:g_wc3h;
        __half *dl = (which==2)?g_wc0l:(which==3)?g_wc1l:(which==4)?g_wc2l:g_wc3l;
        int o = (int)(i / 2304);
        int k = (int)(i - (size_t)o*2304);
        int j = k >> 8, ic = k & 255;
        split2h(src[((size_t)o*256 + ic)*9 + j], dh[i], dl[i]);
    } else if (which == 6){
        if (i >= (size_t)384*256) return;
        int n = (int)(i >> 8), c = (int)(i & 255);
        float v = 0.f;
        if (n < 256)       v = vw[(size_t)c*256 + n];
        else if (n < 320)  v = ow2[(size_t)c*64 + (n-256)];
        else if (n < 352)  v = aw2[(size_t)c*32 + (n-320)];
        split2h(v, g_wcth[i], g_wctl[i]);
        if (c == 0){
            float bv = 0.f;
            if (n < 256) bv = vb2[n];
            else if (n < 320) bv = ob2[n-256];
            else if (n < 352) bv = ab2[n-320];
            g_bct[n] = bv;
        }
    } else {
        if (i >= (size_t)256*256) return;
        int n = (int)(i >> 8), c = (int)(i & 255);
        split2h(outw[(size_t)c*256 + n], g_woh[i], g_wol[i]);
    }
}

// ======================= main GEMM (mma.sync fp16, A-single + B-2term emulation) =====
// CTA tile 128(m) x 128(n) x 32(k). 8 warps (2x4), warp tile 64x32.
// SMEM buffer (24KB): A 8KB: row m(0..127) x 64B, unit-swizzle (u ^= (row>>1)&3);
//                     B 16KB: row n(0..127) x [Bh 64B | Bl 64B], SW128. 3-deep ring.
#define BUFB 24576
#define SMEM_BYTES (3*BUFB)

__global__ __launch_bounds__(256, 2) void k_gemm(int stage, const float* __restrict__ ebias,
                                                 float* __restrict__ dout)
{
    extern __shared__ char smc[];
    const uint32_t sb = smem_u32(smc);
    const int tid = threadIdx.x;
    const int wid = tid >> 5, lid = tid & 31;
    const int b  = blockIdx.z;
    const int l0 = blockIdx.y << 7;
    const int n0 = blockIdx.x << 7;

    int K;
    const __half *wh, *wl;
    switch (stage){
        case 0: K = 512;  wh = g_wcv1h; wl = g_wcv1l; break;
        case 1: K = 2304; wh = g_wc0h;  wl = g_wc0l;  break;
        case 2: K = 2304; wh = g_wc1h;  wl = g_wc1l;  break;
        case 3: K = 2304; wh = g_wc2h;  wl = g_wc2l;  break;
        case 4: K = 2304; wh = g_wc3h;  wl = g_wc3l;  break;
        case 5: K = 256;  wh = g_wcth;  wl = g_wctl;  break;
        case 6: K = 256;  wh = g_woh;   wl = g_wol;   break;
        default:K = 1280; wh = g_wv2h;  wl = g_wv2l;  break;
    }
    const int NC = K >> 5;          // k32 chunks

    float acc[4][4][4];
#pragma unroll
    for (int i=0;i<4;i++)
#pragma unroll
    for (int j=0;j<4;j++)
#pragma unroll
    for (int e=0;e<4;e++) acc[i][j][e] = 0.f;

    const int wm = wid >> 2, wn = wid & 3;

    auto issue = [&](int cc){
        const __half *aa; int ach, acb, ady = 0, adx = 0; bool acv = false;
        const int k0c = cc << 5;
        if (stage == 0){ aa = g_xa; ach = 512; acb = k0c; }
        else if (stage <= 4){
            int j = cc >> 3; int jd = j / 3;
            ady = jd - 1; adx = j - jd*3 - 1; acv = true;
            int ic0 = (cc & 7) << 5;
            if (stage == 1){ aa = g_y0; ach = 512; acb = 256 + ic0; }
            else if (stage == 2){ aa = g_t0; ach = 256; acb = ic0; }
            else if (stage == 3){ aa = g_b1; ach = 256; acb = ic0; }
            else { aa = g_t1; ach = 256; acb = ic0; }
        }
        else if (stage == 5){ aa = g_b2; ach = 256; acb = k0c; }
        else if (stage == 6){ aa = g_sm; ach = 256; acb = k0c; }
        else {
            if (k0c < 512)      { aa = g_y0; ach = 512; acb = k0c; }
            else if (k0c < 768) { aa = g_b1; ach = 256; acb = k0c - 512; }
            else if (k0c < 1024){ aa = g_b2; ach = 256; acb = k0c - 768; }
            else                { aa = g_at; ach = 256; acb = k0c - 1024; }
        }
        uint32_t base = sb + (uint32_t)(cc % 3) * BUFB;
        // ---- A: 128 rows x 64B, 512 16B-units, 2 per thread ----
#pragma unroll
        for (int it2 = 0; it2 < 2; it2++){
            int it = tid + (it2 << 8);        // 0..511
            int m = it >> 2, cu = it & 3;     // row, logical 16B unit
            uint32_t su = (uint32_t)(cu ^ ((m >> 1) & 3));
            uint32_t dst = base + ((uint32_t)m << 6) + (su << 4);
            size_t off = 0; uint32_t nb = 16;
            if (acv){
                int p = l0 + m;
                int sy = (p >> 6) + ady, sx = (p & 63) + adx;
                if ((unsigned)sy < 64u && (unsigned)sx < 64u)
                    off = (size_t)((b<<12) + (sy<<6) + sx) * ach + acb + (cu<<3);
                else nb = 0;
            } else {
                off = (size_t)((b<<12) + l0 + m) * ach + acb + (cu<<3);
            }
            cpa16(dst, aa + off, nb);
        }
        // ---- B: 128 rows x [Bh 64B | Bl 64B], 1024 units, 4 per thread ----
#pragma unroll
        for (int it2 = 0; it2 < 4; it2++){
            int it = tid + (it2 << 8);        // 0..1023
            int n = it >> 3, sub = it & 7;
            int half = sub >> 2, u = sub & 3;
            uint32_t o = ((uint32_t)n << 7) + ((uint32_t)half << 6) + ((uint32_t)u << 4);
            size_t woff = (size_t)(n0 + n) * K + k0c + (u << 3);
            cpa16(base + 8192 + SW128(o), (half ? wl : wh) + woff, 16);
        }
        CP_COMMIT();
    };

    issue(0);
    issue(1);
    for (int cc = 0; cc < NC; cc++){
        CP_WAIT1();
        __syncthreads();
        if (cc + 2 < NC) issue(cc + 2);
        uint32_t ua = sb + (uint32_t)(cc % 3) * BUFB;
        uint32_t ub = ua + 8192u;
        const int mat = lid >> 3, r8 = lid & 7;
#pragma unroll
        for (int ks = 0; ks < 2; ks++){
            uint32_t af[4][4], bh[2][4], bl[2][4];
#pragma unroll
            for (int mi = 0; mi < 4; mi++){
                int row = (wm << 6) + (mi << 4) + ((mat & 1) << 3) + r8;
                uint32_t lu = (uint32_t)((ks << 1) + (mat >> 1));
                uint32_t su = lu ^ ((row >> 1) & 3);
                ldsm4(af[mi], ua + ((uint32_t)row << 6) + (su << 4));
            }
#pragma unroll
            for (int bi = 0; bi < 2; bi++){
                int row = (wn << 5) + (bi << 4) + ((mat >> 1) << 3) + r8;
                uint32_t o = ((uint32_t)row << 7) + ((uint32_t)((ks << 1) + (mat & 1)) << 4);
                ldsm4(bh[bi], ub + SW128(o));
                uint32_t o2 = o + 64;
                ldsm4(bl[bi], ub + SW128(o2));
            }
            // sweep 1: A * Bh
#pragma unroll
            for (int mi = 0; mi < 4; mi++)
#pragma unroll
            for (int ni = 0; ni < 4; ni++)
                mma16816(acc[mi][ni], af[mi],
                         bh[ni >> 1][(ni & 1) << 1], bh[ni >> 1][((ni & 1) << 1) + 1]);
            // sweep 2: A * Bl
#pragma unroll
            for (int mi = 0; mi < 4; mi++)
#pragma unroll
            for (int ni = 0; ni < 4; ni++)
                mma16816(acc[mi][ni], af[mi],
                         bl[ni >> 1][(ni & 1) << 1], bl[ni >> 1][((ni & 1) << 1) + 1]);
        }
    }

    // ---------------- epilogue ----------------
    const int qr = lid >> 2;
    const int qc = (lid & 3) << 1;
#pragma unroll
    for (int mi = 0; mi < 4; mi++){
#pragma unroll
        for (int ni = 0; ni < 4; ni++){
            float* c = acc[mi][ni];
            int ch = (wn << 5) + (ni << 3) + qc;
            int r0 = (wm << 6) + (mi << 4) + qr;
            int r1 = r0 + 8;

            if (stage <= 4){
                __half* dd; int OC;
                if (stage == 0){ dd = g_y0; OC = 512; }
                else if (stage == 1){ dd = g_t0; OC = 256; }
                else if (stage == 2){ dd = g_b1; OC = 256; }
                else if (stage == 3){ dd = g_t1; OC = 256; }
                else { dd = g_b2; OC = 256; }
#pragma unroll
                for (int h2 = 0; h2 < 2; h2++){
                    int r = h2 ? r1 : r0;
                    size_t o = ((size_t)((b<<12) + l0 + r)) * OC + n0 + ch;
                    *(uint32_t*)&dd[o] = packh2(silu_f(c[2*h2]), silu_f(c[2*h2+1]));
                }
            } else if (stage == 5){
#pragma unroll
                for (int h2 = 0; h2 < 2; h2++){
                    int r = h2 ? r1 : r0;
                    size_t bl2 = (size_t)(b<<12) + l0 + r;
#pragma unroll
                    for (int e = 0; e < 2; e++){
                        int ng = n0 + ch + e;
                        float v = c[2*h2 + e] + g_bct[ng];
                        if (ng < 256)      g_value[bl2*256 + ng] = v;
                        else if (ng < 320) g_off [bl2*64 + (ng - 256)] = v;
                        else if (ng < 352) g_awL [bl2*32 + (ng - 320)] = v;
                    }
                }
            } else if (stage == 6){
#pragma unroll
                for (int h2 = 0; h2 < 2; h2++){
                    int r = h2 ? r1 : r0;
                    float v0 = c[2*h2]     + ebias[n0 + ch];
                    float v1 = c[2*h2 + 1] + ebias[n0 + ch + 1];
                    size_t o = ((size_t)((b<<12) + l0 + r)) * 256 + n0 + ch;
                    *(uint32_t*)&g_at[o] = packh2(v0, v1);
                }
            } else {
#pragma unroll
                for (int h2 = 0; h2 < 2; h2++){
                    int r = h2 ? r1 : r0;
#pragma unroll
                    for (int e = 0; e < 2; e++){
                        float v = silu_f(c[2*h2 + e]);
                        dout[((size_t)((b << 9) + n0 + ch + e) << 12) + l0 + r] = v;
                    }
                }
            }
        }
    }
}

// ======================= deformable sampling =======================
__global__ void k_sample(const float* __restrict__ bbox){
    int g = blockIdx.x * blockDim.x + threadIdx.x;
    if (g >= NB * LP * 64) return;
    int d4 = g & 7;
    int hd = (g >> 3) & 7;
    int l  = (g >> 6) & 4095;
    int b  = g >> 18;
    size_t bl = (size_t)b * LP + l;
    float bx = bbox[bl*2 + 0];
    float by = bbox[bl*2 + 1];
    const float* op = g_off + bl*64 + hd*8;
    const float* ap = g_awL + bl*32 + hd*4;

    float a0 = ap[0], a1 = ap[1], a2 = ap[2], a3 = ap[3];
    float mx = fmaxf(fmaxf(a0, a1), fmaxf(a2, a3));
    float e0 = __expf(a0 - mx), e1 = __expf(a1 - mx), e2 = __expf(a2 - mx), e3 = __expf(a3 - mx);
    float inv = 1.f / (e0 + e1 + e2 + e3);
    float wp[4] = {e0*inv, e1*inv, e2*inv, e3*inv};

    const float* vb = g_value + ((size_t)b * LP) * 256 + hd*32 + (d4 << 2);
    float4 acc = make_float4(0.f, 0.f, 0.f, 0.f);
#pragma unroll
    for (int p = 0; p < 4; p++){
        float lx = bx + op[p*2 + 0] * 0.015625f;
        float ly = by + op[p*2 + 1] * 0.015625f;
        float gx = lx * 64.f - 0.5f;
        float gy = ly * 64.f - 0.5f;
        float fx = floorf(gx), fy = floorf(gy);
        float wx1 = gx - fx, wy1 = gy - fy;
        float wx0 = 1.f - wx1, wy0 = 1.f - wy1;
        int ix = (int)fx, iy = (int)fy;
        float awp = wp[p];
#pragma unroll
        for (int c2 = 0; c2 < 4; c2++){
            int cx = ix + (c2 & 1);
            int cy = iy + (c2 >> 1);
            if ((unsigned)cx < 64u && (unsigned)cy < 64u){
                float wgt = awp * ((c2 & 1) ? wx1 : wx0) * ((c2 >> 1) ? wy1 : wy0);
                float4 v = *(const float4*)&vb[(size_t)((cy << 6) + cx) * 256];
                acc.x += wgt * v.x; acc.y += wgt * v.y;
                acc.z += wgt * v.z; acc.w += wgt * v.w;
            }
        }
    }
    size_t o = bl*256 + hd*32 + (d4 << 2);
    *(uint32_t*)&g_sm[o]     = packh2(acc.x, acc.y);
    *(uint32_t*)&g_sm[o + 2] = packh2(acc.z, acc.w);
}

// ======================= launch =======================
extern "C" void kernel_launch(void* const* d_in, const int* in_sizes, int n_in,
                              void* d_out, int out_size) {
    const float* x    = (const float*)d_in[0];
    const float* bbox = (const float*)d_in[1];
    const float* cv1w = (const float*)d_in[3];
    const float* m0c1 = (const float*)d_in[4];
    const float* m0c2 = (const float*)d_in[5];
    const float* m1c1 = (const float*)d_in[6];
    const float* m1c2 = (const float*)d_in[7];
    const float* vw   = (const float*)d_in[8];
    const float* vb   = (const float*)d_in[9];
    const float* ow   = (const float*)d_in[10];
    const float* ob   = (const float*)d_in[11];
    const float* aww  = (const float*)d_in[12];
    const float* awb  = (const float*)d_in[13];
    const float* outw = (const float*)d_in[14];
    const float* outb = (const float*)d_in[15];
    const float* cv2w = (const float*)d_in[16];

    cudaFuncSetAttribute(k_gemm, cudaFuncAttributeMaxDynamicSharedMemorySize, SMEM_BYTES);

    k_cvt_x<<<dim3(128, 16, NB), dim3(32, 8)>>>(x);
    k_cvt_w<<<dim3(2560, 8), 256>>>(cv1w, cv2w, m0c1, m0c2, m1c1, m1c2,
                                    vw, vb, ow, ob, aww, awb, outw);

    k_gemm<<<dim3(4, 32, NB), 256, SMEM_BYTES>>>(0, nullptr, nullptr);   // cv1
    k_gemm<<<dim3(2, 32, NB), 256, SMEM_BYTES>>>(1, nullptr, nullptr);   // m0_cv1
    k_gemm<<<dim3(2, 32, NB), 256, SMEM_BYTES>>>(2, nullptr, nullptr);   // m0_cv2
    k_gemm<<<dim3(2, 32, NB), 256, SMEM_BYTES>>>(3, nullptr, nullptr);   // m1_cv1
    k_gemm<<<dim3(2, 32, NB), 256, SMEM_BYTES>>>(4, nullptr, nullptr);   // m1_cv2
    k_gemm<<<dim3(3, 32, NB), 256, SMEM_BYTES>>>(5, nullptr, nullptr);   // fused projections
    k_sample<<<(NB * LP * 64 + 255) / 256, 256>>>(bbox);
    k_gemm<<<dim3(2, 32, NB), 256, SMEM_BYTES>>>(6, outb, nullptr);      // out projection
    k_gemm<<<dim3(4, 32, NB), 256, SMEM_BYTES>>>(7, nullptr, (float*)d_out); // cv2
}

// round 9
// speedup vs baseline: 8.1859x; 1.7900x over previous
#include <cuda_runtime.h>
#include <cuda_fp16.h>
#include <cstdint>

#define NB 8
#define LP 4096

// ======================= PTX helpers (baseline ISA only) =======================
__device__ __forceinline__ uint32_t smem_u32(const void* p){
    uint32_t a;
    asm("{ .reg .u64 t; cvta.to.shared.u64 t, %1; cvt.u32.u64 %0, t; }" : "=r"(a) : "l"(p));
    return a;
}
__device__ __forceinline__ void cpa16(uint32_t dst, const void* src, uint32_t nbytes){
    asm volatile("cp.async.cg.shared.global [%0], [%1], 16, %2;"
        :: "r"(dst), "l"(src), "r"(nbytes) : "memory");
}
#define CP_COMMIT() asm volatile("cp.async.commit_group;" ::: "memory")
#define CP_WAIT1()  asm volatile("cp.async.wait_group 1;" ::: "memory")

__device__ __forceinline__ void ldsm4(uint32_t* r, uint32_t a){
    asm volatile("ldmatrix.sync.aligned.m8n8.x4.shared.b16 {%0,%1,%2,%3}, [%4];"
        : "=r"(r[0]), "=r"(r[1]), "=r"(r[2]), "=r"(r[3]) : "r"(a));
}
__device__ __forceinline__ void mma16816(float* c, const uint32_t* a, uint32_t b0, uint32_t b1){
    asm volatile("mma.sync.aligned.m16n8k16.row.col.f32.f16.f16.f32 "
        "{%0,%1,%2,%3}, {%4,%5,%6,%7}, {%8,%9}, {%0,%1,%2,%3};"
        : "+f"(c[0]), "+f"(c[1]), "+f"(c[2]), "+f"(c[3])
        : "r"(a[0]), "r"(a[1]), "r"(a[2]), "r"(a[3]), "r"(b0), "r"(b1));
}
#define SW128(o) ((o) ^ (((o) >> 3) & 0x70))

// ======================= device scratch =======================
// activations: single fp16, channel-contiguous [b][l][c]
__device__ __half g_xa[(size_t)NB*LP*512];
__device__ __half g_y0[(size_t)NB*LP*512];
__device__ __half g_t0[(size_t)NB*LP*256];
__device__ __half g_b1[(size_t)NB*LP*256];
__device__ __half g_t1[(size_t)NB*LP*256];
__device__ __half g_b2[(size_t)NB*LP*256];
__device__ float g_value[(size_t)NB*LP*256];
__device__ float g_off [(size_t)NB*LP*64];
__device__ float g_awL [(size_t)NB*LP*32];
__device__ __half g_sm[(size_t)NB*LP*256];
__device__ __half g_at[(size_t)NB*LP*256];

// weights: single fp16
__device__ __half g_wcv1[512*512];
__device__ __half g_wc0[256*2304];
__device__ __half g_wc1[256*2304];
__device__ __half g_wc2[256*2304];
__device__ __half g_wc3[256*2304];
__device__ __half g_wct[384*256];
__device__ float  g_bct[384];
__device__ __half g_wo[256*256];
__device__ __half g_wv2[512*1280];

__device__ __forceinline__ float silu_f(float v){ return v / (1.f + __expf(-v)); }
__device__ __forceinline__ uint32_t packh2(float a, float b){
    __half2 hh = __floats2half2_rn(a, b);
    return *(uint32_t*)&hh;
}

// ======================= conversion kernels =======================
__global__ void k_cvt_x(const float* __restrict__ x){
    __shared__ float t[32][33];
    int b = blockIdx.z, l0 = blockIdx.x<<5, c0 = blockIdx.y<<5;
    int tx = threadIdx.x, ty = threadIdx.y;
#pragma unroll
    for (int i=0;i<32;i+=8)
        t[ty+i][tx] = x[((size_t)((b<<9)+(c0+ty+i))<<12) + l0 + tx];
    __syncthreads();
#pragma unroll
    for (int i=0;i<32;i+=8){
        size_t o = ((size_t)((b<<12)+(l0+ty+i))<<9) + c0 + tx;
        g_xa[o] = __float2half(t[tx][ty+i]);
    }
}

// all weight conversions in one launch; branch on blockIdx.y
__global__ void k_cvt_w(const float* __restrict__ cv1w, const float* __restrict__ cv2w,
                        const float* __restrict__ c0, const float* __restrict__ c1,
                        const float* __restrict__ c2, const float* __restrict__ c3,
                        const float* __restrict__ vw, const float* __restrict__ vb2,
                        const float* __restrict__ ow2, const float* __restrict__ ob2,
                        const float* __restrict__ aw2, const float* __restrict__ ab2,
                        const float* __restrict__ outw){
    int which = blockIdx.y;
    size_t i = (size_t)blockIdx.x*256 + threadIdx.x;
    if (which == 0){
        if (i >= (size_t)512*512) return;
        g_wcv1[i] = __float2half(cv1w[i]);
    } else if (which == 1){
        if (i >= (size_t)512*1280) return;
        g_wv2[i] = __float2half(cv2w[i]);
    } else if (which <= 5){
        if (i >= (size_t)256*2304) return;
        const float* src = (which==2)?c0:(which==3)?c1:(which==4)?c2:c3;
        __half *dh = (which==2)?g_wc0:(which==3)?g_wc1:(which==4)?g_wc2:g_wc3;
        int o = (int)(i / 2304);
        int k = (int)(i - (size_t)o*2304);
        int j = k >> 8, ic = k & 255;
        dh[i] = __float2half(src[((size_t)o*256 + ic)*9 + j]);
    } else if (which == 6){
        if (i >= (size_t)384*256) return;
        int n = (int)(i >> 8), c = (int)(i & 255);
        float v = 0.f;
        if (n < 256)       v = vw[(size_t)c*256 + n];
        else if (n < 320)  v = ow2[(size_t)c*64 + (n-256)];
        else if (n < 352)  v = aw2[(size_t)c*32 + (n-320)];
        g_wct[i] = __float2half(v);
        if (c == 0){
            float bv = 0.f;
            if (n < 256) bv = vb2[n];
            else if (n < 320) bv = ob2[n-256];
            else if (n < 352) bv = ab2[n-320];
            g_bct[n] = bv;
        }
    } else {
        if (i >= (size_t)256*256) return;
        int n = (int)(i >> 8), c = (int)(i & 255);
        g_wo[i] = __float2half(outw[(size_t)c*256 + n]);
    }
}

// ======================= main GEMM (pure fp16 mma.sync, fp32 accum) =======================
// CTA tile 128(m) x 128(n) x 64(k). 8 warps (2x4), warp tile 64x32.
// SMEM buffer (32KB): A 16KB (128 rows x 128B, SW128); B 16KB same. 3-deep ring, 2 CTAs/SM.
#define BUFB 32768
#define SMEM_BYTES (3*BUFB)

__global__ __launch_bounds__(256, 2) void k_gemm(int stage, const float* __restrict__ ebias,
                                                 float* __restrict__ dout)
{
    extern __shared__ char smc[];
    const uint32_t sb = smem_u32(smc);
    const int tid = threadIdx.x;
    const int wid = tid >> 5, lid = tid & 31;
    const int b  = blockIdx.z;
    const int l0 = blockIdx.y << 7;
    const int n0 = blockIdx.x << 7;

    int K;
    const __half* wgt;
    switch (stage){
        case 0: K = 512;  wgt = g_wcv1; break;
        case 1: K = 2304; wgt = g_wc0;  break;
        case 2: K = 2304; wgt = g_wc1;  break;
        case 3: K = 2304; wgt = g_wc2;  break;
        case 4: K = 2304; wgt = g_wc3;  break;
        case 5: K = 256;  wgt = g_wct;  break;
        case 6: K = 256;  wgt = g_wo;   break;
        default:K = 1280; wgt = g_wv2;  break;
    }
    const int NC = K >> 6;          // k64 chunks

    float acc[4][4][4];
#pragma unroll
    for (int i=0;i<4;i++)
#pragma unroll
    for (int j=0;j<4;j++)
#pragma unroll
    for (int e=0;e<4;e++) acc[i][j][e] = 0.f;

    const int wm = wid >> 2, wn = wid & 3;

    auto issue = [&](int cc){
        const __half *aa; int ach, acb, ady = 0, adx = 0; bool acv = false;
        const int k0c = cc << 6;
        if (stage == 0){ aa = g_xa; ach = 512; acb = k0c; }
        else if (stage <= 4){
            int j = cc >> 2; int jd = j / 3;
            ady = jd - 1; adx = j - jd*3 - 1; acv = true;
            int ic0 = (cc & 3) << 6;
            if (stage == 1){ aa = g_y0; ach = 512; acb = 256 + ic0; }
            else if (stage == 2){ aa = g_t0; ach = 256; acb = ic0; }
            else if (stage == 3){ aa = g_b1; ach = 256; acb = ic0; }
            else { aa = g_t1; ach = 256; acb = ic0; }
        }
        else if (stage == 5){ aa = g_b2; ach = 256; acb = k0c; }
        else if (stage == 6){ aa = g_sm; ach = 256; acb = k0c; }
        else {
            if (k0c < 512)      { aa = g_y0; ach = 512; acb = k0c; }
            else if (k0c < 768) { aa = g_b1; ach = 256; acb = k0c - 512; }
            else if (k0c < 1024){ aa = g_b2; ach = 256; acb = k0c - 768; }
            else                { aa = g_at; ach = 256; acb = k0c - 1024; }
        }
        uint32_t base = sb + (uint32_t)(cc % 3) * BUFB;
        // ---- A: 128 rows x 128B SW128, 1024 units, 4 per thread ----
#pragma unroll
        for (int it2 = 0; it2 < 4; it2++){
            int it = tid + (it2 << 8);        // 0..1023
            int m = it >> 3, u = it & 7;      // row, 16B unit
            uint32_t o = ((uint32_t)m << 7) + ((uint32_t)u << 4);
            size_t off = 0; uint32_t nb = 16;
            if (acv){
                int p = l0 + m;
                int sy = (p >> 6) + ady, sx = (p & 63) + adx;
                if ((unsigned)sy < 64u && (unsigned)sx < 64u)
                    off = (size_t)((b<<12) + (sy<<6) + sx) * ach + acb + (u<<3);
                else nb = 0;
            } else {
                off = (size_t)((b<<12) + l0 + m) * ach + acb + (u<<3);
            }
            cpa16(base + SW128(o), aa + off, nb);
        }
        // ---- B: 128 rows x 128B SW128 ----
#pragma unroll
        for (int it2 = 0; it2 < 4; it2++){
            int it = tid + (it2 << 8);
            int n = it >> 3, u = it & 7;
            uint32_t o = ((uint32_t)n << 7) + ((uint32_t)u << 4);
            size_t woff = (size_t)(n0 + n) * K + k0c + (u << 3);
            cpa16(base + 16384 + SW128(o), wgt + woff, 16);
        }
        CP_COMMIT();
    };

    issue(0);
    issue(1);
    for (int cc = 0; cc < NC; cc++){
        CP_WAIT1();
        __syncthreads();
        if (cc + 2 < NC) issue(cc + 2);
        uint32_t ua = sb + (uint32_t)(cc % 3) * BUFB;
        uint32_t ub = ua + 16384u;
        const int mat = lid >> 3, r8 = lid & 7;
#pragma unroll
        for (int ks = 0; ks < 4; ks++){
            uint32_t af[4][4], bf[2][4];
#pragma unroll
            for (int mi = 0; mi < 4; mi++){
                int row = (wm << 6) + (mi << 4) + ((mat & 1) << 3) + r8;
                uint32_t o = ((uint32_t)row << 7) + (ks << 5) + ((mat >> 1) << 4);
                ldsm4(af[mi], ua + SW128(o));
            }
#pragma unroll
            for (int bi = 0; bi < 2; bi++){
                int row = (wn << 5) + (bi << 4) + ((mat >> 1) << 3) + r8;
                uint32_t o = ((uint32_t)row << 7) + (ks << 5) + ((mat & 1) << 4);
                ldsm4(bf[bi], ub + SW128(o));
            }
#pragma unroll
            for (int mi = 0; mi < 4; mi++)
#pragma unroll
            for (int ni = 0; ni < 4; ni++)
                mma16816(acc[mi][ni], af[mi],
                         bf[ni >> 1][(ni & 1) << 1], bf[ni >> 1][((ni & 1) << 1) + 1]);
        }
    }

    // ---------------- epilogue ----------------
    const int qr = lid >> 2;
    const int qc = (lid & 3) << 1;
#pragma unroll
    for (int mi = 0; mi < 4; mi++){
#pragma unroll
        for (int ni = 0; ni < 4; ni++){
            float* c = acc[mi][ni];
            int ch = (wn << 5) + (ni << 3) + qc;
            int r0 = (wm << 6) + (mi << 4) + qr;
            int r1 = r0 + 8;

            if (stage <= 4){
                __half* dd; int OC;
                if (stage == 0){ dd = g_y0; OC = 512; }
                else if (stage == 1){ dd = g_t0; OC = 256; }
                else if (stage == 2){ dd = g_b1; OC = 256; }
                else if (stage == 3){ dd = g_t1; OC = 256; }
                else { dd = g_b2; OC = 256; }
#pragma unroll
                for (int h2 = 0; h2 < 2; h2++){
                    int r = h2 ? r1 : r0;
                    size_t o = ((size_t)((b<<12) + l0 + r)) * OC + n0 + ch;
                    *(uint32_t*)&dd[o] = packh2(silu_f(c[2*h2]), silu_f(c[2*h2+1]));
                }
            } else if (stage == 5){
#pragma unroll
                for (int h2 = 0; h2 < 2; h2++){
                    int r = h2 ? r1 : r0;
                    size_t bl2 = (size_t)(b<<12) + l0 + r;
#pragma unroll
                    for (int e = 0; e < 2; e++){
                        int ng = n0 + ch + e;
                        float v = c[2*h2 + e] + g_bct[ng];
                        if (ng < 256)      g_value[bl2*256 + ng] = v;
                        else if (ng < 320) g_off [bl2*64 + (ng - 256)] = v;
                        else if (ng < 352) g_awL [bl2*32 + (ng - 320)] = v;
                    }
                }
            } else if (stage == 6){
#pragma unroll
                for (int h2 = 0; h2 < 2; h2++){
                    int r = h2 ? r1 : r0;
                    float v0 = c[2*h2]     + ebias[n0 + ch];
                    float v1 = c[2*h2 + 1] + ebias[n0 + ch + 1];
                    size_t o = ((size_t)((b<<12) + l0 + r)) * 256 + n0 + ch;
                    *(uint32_t*)&g_at[o] = packh2(v0, v1);
                }
            } else {
#pragma unroll
                for (int h2 = 0; h2 < 2; h2++){
                    int r = h2 ? r1 : r0;
#pragma unroll
                    for (int e = 0; e < 2; e++){
                        float v = silu_f(c[2*h2 + e]);
                        dout[((size_t)((b << 9) + n0 + ch + e) << 12) + l0 + r] = v;
                    }
                }
            }
        }
    }
}

// ======================= deformable sampling =======================
__global__ void k_sample(const float* __restrict__ bbox){
    int g = blockIdx.x * blockDim.x + threadIdx.x;
    if (g >= NB * LP * 64) return;
    int d4 = g & 7;
    int hd = (g >> 3) & 7;
    int l  = (g >> 6) & 4095;
    int b  = g >> 18;
    size_t bl = (size_t)b * LP + l;
    float bx = bbox[bl*2 + 0];
    float by = bbox[bl*2 + 1];
    const float* op = g_off + bl*64 + hd*8;
    const float* ap = g_awL + bl*32 + hd*4;

    float a0 = ap[0], a1 = ap[1], a2 = ap[2], a3 = ap[3];
    float mx = fmaxf(fmaxf(a0, a1), fmaxf(a2, a3));
    float e0 = __expf(a0 - mx), e1 = __expf(a1 - mx), e2 = __expf(a2 - mx), e3 = __expf(a3 - mx);
    float inv = 1.f / (e0 + e1 + e2 + e3);
    float wp[4] = {e0*inv, e1*inv, e2*inv, e3*inv};

    const float* vb = g_value + ((size_t)b * LP) * 256 + hd*32 + (d4 << 2);
    float4 acc = make_float4(0.f, 0.f, 0.f, 0.f);
#pragma unroll
    for (int p = 0; p < 4; p++){
        float lx = bx + op[p*2 + 0] * 0.015625f;
        float ly = by + op[p*2 + 1] * 0.015625f;
        float gx = lx * 64.f - 0.5f;
        float gy = ly * 64.f - 0.5f;
        float fx = floorf(gx), fy = floorf(gy);
        float wx1 = gx - fx, wy1 = gy - fy;
        float wx0 = 1.f - wx1, wy0 = 1.f - wy1;
        int ix = (int)fx, iy = (int)fy;
        float awp = wp[p];
#pragma unroll
        for (int c2 = 0; c2 < 4; c2++){
            int cx = ix + (c2 & 1);
            int cy = iy + (c2 >> 1);
            if ((unsigned)cx < 64u && (unsigned)cy < 64u){
                float wgt = awp * ((c2 & 1) ? wx1 : wx0) * ((c2 >> 1) ? wy1 : wy0);
                float4 v = *(const float4*)&vb[(size_t)((cy << 6) + cx) * 256];
                acc.x += wgt * v.x; acc.y += wgt * v.y;
                acc.z += wgt * v.z; acc.w += wgt * v.w;
            }
        }
    }
    size_t o = bl*256 + hd*32 + (d4 << 2);
    *(uint32_t*)&g_sm[o]     = packh2(acc.x, acc.y);
    *(uint32_t*)&g_sm[o + 2] = packh2(acc.z, acc.w);
}

// ======================= launch =======================
extern "C" void kernel_launch(void* const* d_in, const int* in_sizes, int n_in,
                              void* d_out, int out_size) {
    const float* x    = (const float*)d_in[0];
    const float* bbox = (const float*)d_in[1];
    const float* cv1w = (const float*)d_in[3];
    const float* m0c1 = (const float*)d_in[4];
    const float* m0c2 = (const float*)d_in[5];
    const float* m1c1 = (const float*)d_in[6];
    const float* m1c2 = (const float*)d_in[7];
    const float* vw   = (const float*)d_in[8];
    const float* vb   = (const float*)d_in[9];
    const float* ow   = (const float*)d_in[10];
    const float* ob   = (const float*)d_in[11];
    const float* aww  = (const float*)d_in[12];
    const float* awb  = (const float*)d_in[13];
    const float* outw = (const float*)d_in[14];
    const float* outb = (const float*)d_in[15];
    const float* cv2w = (const float*)d_in[16];

    cudaFuncSetAttribute(k_gemm, cudaFuncAttributeMaxDynamicSharedMemorySize, SMEM_BYTES);

    k_cvt_x<<<dim3(128, 16, NB), dim3(32, 8)>>>(x);
    k_cvt_w<<<dim3(2560, 8), 256>>>(cv1w, cv2w, m0c1, m0c2, m1c1, m1c2,
                                    vw, vb, ow, ob, aww, awb, outw);

    k_gemm<<<dim3(4, 32, NB), 256, SMEM_BYTES>>>(0, nullptr, nullptr);   // cv1
    k_gemm<<<dim3(2, 32, NB), 256, SMEM_BYTES>>>(1, nullptr, nullptr);   // m0_cv1
    k_gemm<<<dim3(2, 32, NB), 256, SMEM_BYTES>>>(2, nullptr, nullptr);   // m0_cv2
    k_gemm<<<dim3(2, 32, NB), 256, SMEM_BYTES>>>(3, nullptr, nullptr);   // m1_cv1
    k_gemm<<<dim3(2, 32, NB), 256, SMEM_BYTES>>>(4, nullptr, nullptr);   // m1_cv2
    k_gemm<<<dim3(3, 32, NB), 256, SMEM_BYTES>>>(5, nullptr, nullptr);   // fused projections
    k_sample<<<(NB * LP * 64 + 255) / 256, 256>>>(bbox);
    k_gemm<<<dim3(2, 32, NB), 256, SMEM_BYTES>>>(6, outb, nullptr);      // out projection
    k_gemm<<<dim3(4, 32, NB), 256, SMEM_BYTES>>>(7, nullptr, (float*)d_out); // cv2
}